// round 2
// baseline (speedup 1.0000x reference)
#include <cuda_runtime.h>
#include <cstdint>
#include <math.h>

// Problem constants (fixed by dataset)
#define NB 16384
#define NC 5
#define NH 256
#define NV 512
#define NCV (NC*NV)               // 2560
#define NBH (NB*NH)               // 4194304
#define NBCV (41943040u)          // NB*NC*NV
#define TINYF 1.17549435082228751e-38f

// JAX PRNG mode: 1 = threefry_partitionable (default since jax 0.4.36), 0 = legacy
#define JAX_PARTITIONABLE 1

// ---------------- scratch (static device globals; no allocations) ----------------
__device__ float   g_h[NBH];                    // current h sample (0/1)
__device__ float   g_logits[(size_t)NB * NCV];  // GEMM output for sample_v
__device__ float   g_Wt[NC * NV * NH];          // W transposed to [c][v][h] (h contiguous)
__device__ uint8_t g_idx[(size_t)NB * NV];      // current v category, layout [b][v]

// ---------------- threefry2x32 (bit-exact with JAX / Random123) ----------------
__host__ __device__ __forceinline__ uint32_t rotl32(uint32_t x, int r) {
#ifdef __CUDA_ARCH__
    return __funnelshift_l(x, x, r);
#else
    return (x << r) | (x >> (32 - r));
#endif
}

__host__ __device__ inline void threefry(uint32_t k0, uint32_t k1,
                                         uint32_t x0, uint32_t x1,
                                         uint32_t& o0, uint32_t& o1) {
    uint32_t k2 = k0 ^ k1 ^ 0x1BD11BDAu;
#define TFR(r) { x0 += x1; x1 = rotl32(x1, (r)); x1 ^= x0; }
    x0 += k0; x1 += k1;
    TFR(13) TFR(15) TFR(26) TFR(6)   x0 += k1; x1 += k2 + 1u;
    TFR(17) TFR(29) TFR(16) TFR(24)  x0 += k2; x1 += k0 + 2u;
    TFR(13) TFR(15) TFR(26) TFR(6)   x0 += k0; x1 += k1 + 3u;
    TFR(17) TFR(29) TFR(16) TFR(24)  x0 += k1; x1 += k2 + 4u;
    TFR(13) TFR(15) TFR(26) TFR(6)   x0 += k2; x1 += k0 + 5u;
#undef TFR
    o0 = x0; o1 = x1;
}

// 32-bit random bits for flat element i of an array of 2*half_total elements.
__device__ __forceinline__ uint32_t rand_bits(uint32_t k0, uint32_t k1,
                                              uint32_t i, uint32_t half_total) {
    uint32_t a, b;
#if JAX_PARTITIONABLE
    threefry(k0, k1, 0u, i, a, b);     // 64-bit counter (hi=0, lo=i)
    return a ^ b;                      // 32-bit fold
#else
    if (i < half_total) { threefry(k0, k1, i, i + half_total, a, b); return a; }
    else                { threefry(k0, k1, i - half_total, i, a, b); return b; }
#endif
}

__device__ __forceinline__ float bits_to_unit(uint32_t bits) {
    // jax.random.uniform: bitcast((bits>>9)|0x3f800000) - 1.0
    return __fadd_rn(__uint_as_float((bits >> 9) | 0x3f800000u), -1.0f);
}

// ---------------- kernels ----------------

// Wt[(c*V+v)*H + h] = W[(c*H+h)*V + v]
__global__ void k_transpose(const float* __restrict__ W) {
    int o = blockIdx.x * 256 + threadIdx.x;   // over NC*NV*NH
    int h = o & (NH - 1);
    int r = o >> 8;                           // c*V + v
    int v = r & (NV - 1);
    int c = r >> 9;
    g_Wt[o] = W[((size_t)(c * NH + h)) * NV + v];
}

// g_idx[b*V+v] = argmax_c v0[b,c,v]  (v0 is exact one-hot)
__global__ void k_extract_idx(const float* __restrict__ v0) {
    int i = blockIdx.x * 256 + threadIdx.x;   // over B*V
    int b = i >> 9;
    int v = i & (NV - 1);
    uint32_t c = 0;
#pragma unroll
    for (int cc = 1; cc < NC; cc++)
        if (v0[((size_t)(b * NC + cc)) * NV + v] > 0.5f) c = cc;
    g_idx[(size_t)b * NV + v] = (uint8_t)c;
}

// p[b,h] = sigmoid(sum_v W[idx(b,v),h,v] + c1[h]);  h[b,h] = (u < p)
// Block: 256 threads (one h each), BT=64 b-rows accumulated in registers.
#define BT 64
__global__ __launch_bounds__(256, 2)
void k_sample_h(uint32_t k0, uint32_t k1,
                const float* __restrict__ cvec,
                float* __restrict__ extra_out) {
    __shared__ float    wbuf[4 * NC * NH];   // [j][c][h], 20 KB
    __shared__ uint32_t pk[BT];              // 4 packed idx bytes per b
    const int h  = threadIdx.x;
    const int b0 = blockIdx.x * BT;

    float acc[BT];
#pragma unroll
    for (int i = 0; i < BT; i++) acc[i] = 0.0f;

#pragma unroll 1
    for (int v = 0; v < NV; v += 4) {
        __syncthreads();
#pragma unroll
        for (int j = 0; j < 4; j++)
#pragma unroll
            for (int c = 0; c < NC; c++)
                wbuf[(j * NC + c) * NH + h] =
                    g_Wt[((size_t)(c * NV + v + j)) * NH + h];
        if (h < BT)
            pk[h] = *(const uint32_t*)(g_idx + (size_t)(b0 + h) * NV + v);
        __syncthreads();
#pragma unroll
        for (int bb = 0; bb < BT; bb++) {
            uint32_t p = pk[bb];
#pragma unroll
            for (int j = 0; j < 4; j++) {
                uint32_t c = (p >> (8 * j)) & 0xffu;
                acc[bb] += wbuf[(j * NC + c) * NH + h];
            }
        }
    }

    const float cb = cvec[h];
#pragma unroll 4
    for (int bb = 0; bb < BT; bb++) {
        float x = __fadd_rn(acc[bb], cb);
        // XLA logistic expansion: 0.5*tanh(0.5x) + 0.5
        float t = tanhf(__fmul_rn(0.5f, x));
        float p = __fadd_rn(__fmul_rn(0.5f, t), 0.5f);
        uint32_t gi = (uint32_t)(b0 + bb) * NH + h;
        uint32_t bits = rand_bits(k0, k1, gi, NBH / 2);
        float u = bits_to_unit(bits);
        float hv = (u < p) ? 1.0f : 0.0f;
        g_h[gi] = hv;
        if (extra_out) extra_out[gi] = hv;
    }
}

// logits[b, cv] = sum_h g_h[b,h] * g_Wt[cv,h]   (SGEMM-NT 16384 x 2560 x 256)
__global__ __launch_bounds__(256, 2)
void k_gemm() {
    __shared__ float As[16][128];
    __shared__ float Bs[16][128];
    const int tid = threadIdx.x;
    const int bn = blockIdx.x * 128;        // cv
    const int bm = blockIdx.y * 128;        // b
    const int lr = tid >> 2;                // 0..63
    const int lk = (tid & 3) * 4;           // 0,4,8,12
    const int tm = (tid >> 4) << 3;         // 0..120
    const int tn = (tid & 15) << 3;         // 0..120

    float acc[8][8];
#pragma unroll
    for (int i = 0; i < 8; i++)
#pragma unroll
        for (int j = 0; j < 8; j++) acc[i][j] = 0.0f;

#pragma unroll 1
    for (int kk = 0; kk < NH; kk += 16) {
        float4 a0 = *(const float4*)(g_h  + (size_t)(bm + lr)      * NH + kk + lk);
        float4 a1 = *(const float4*)(g_h  + (size_t)(bm + lr + 64) * NH + kk + lk);
        float4 b0 = *(const float4*)(g_Wt + (size_t)(bn + lr)      * NH + kk + lk);
        float4 b1 = *(const float4*)(g_Wt + (size_t)(bn + lr + 64) * NH + kk + lk);
        __syncthreads();
        As[lk + 0][lr] = a0.x; As[lk + 1][lr] = a0.y;
        As[lk + 2][lr] = a0.z; As[lk + 3][lr] = a0.w;
        As[lk + 0][lr + 64] = a1.x; As[lk + 1][lr + 64] = a1.y;
        As[lk + 2][lr + 64] = a1.z; As[lk + 3][lr + 64] = a1.w;
        Bs[lk + 0][lr] = b0.x; Bs[lk + 1][lr] = b0.y;
        Bs[lk + 2][lr] = b0.z; Bs[lk + 3][lr] = b0.w;
        Bs[lk + 0][lr + 64] = b1.x; Bs[lk + 1][lr + 64] = b1.y;
        Bs[lk + 2][lr + 64] = b1.z; Bs[lk + 3][lr + 64] = b1.w;
        __syncthreads();
#pragma unroll
        for (int k = 0; k < 16; k++) {
            float4 x0 = *(const float4*)&As[k][tm];
            float4 x1 = *(const float4*)&As[k][tm + 4];
            float4 y0 = *(const float4*)&Bs[k][tn];
            float4 y1 = *(const float4*)&Bs[k][tn + 4];
            float xa[8] = {x0.x, x0.y, x0.z, x0.w, x1.x, x1.y, x1.z, x1.w};
            float yb[8] = {y0.x, y0.y, y0.z, y0.w, y1.x, y1.y, y1.z, y1.w};
#pragma unroll
            for (int i = 0; i < 8; i++)
#pragma unroll
                for (int j = 0; j < 8; j++)
                    acc[i][j] += xa[i] * yb[j];
        }
    }
#pragma unroll
    for (int i = 0; i < 8; i++) {
        float* row = g_logits + (size_t)(bm + tm + i) * NCV + bn + tn;
        *(float4*)(row)     = make_float4(acc[i][0], acc[i][1], acc[i][2], acc[i][3]);
        *(float4*)(row + 4) = make_float4(acc[i][4], acc[i][5], acc[i][6], acc[i][7]);
    }
}

// Gumbel-argmax categorical over c for each (b,v); optionally emit one-hot v.
__global__ void k_categorical(uint32_t k0, uint32_t k1,
                              const float* __restrict__ bvec,
                              float* __restrict__ vout, int write_out) {
    int i = blockIdx.x * 256 + threadIdx.x;   // over B*V
    int b = i >> 9;
    int v = i & (NV - 1);

    float best = 0.0f;
    uint32_t bc = 0;
#pragma unroll
    for (int c = 0; c < NC; c++) {
        float l = __fadd_rn(g_logits[(size_t)b * NCV + c * NV + v],
                            bvec[c * NV + v]);
        uint32_t gi = ((uint32_t)b * NC + c) * NV + v;   // < 2^32
        uint32_t bits = rand_bits(k0, k1, gi, NBCV / 2);
        float u = bits_to_unit(bits);
        float up = fmaxf(__fadd_rn(u, TINYF), TINYF);    // uniform(tiny, 1)
        float gmb = -logf(-logf(up));
        float s = __fadd_rn(gmb, l);
        if (c == 0 || s > best) { best = s; bc = (uint32_t)c; }
    }
    g_idx[(size_t)b * NV + v] = (uint8_t)bc;
    if (write_out) {
#pragma unroll
        for (int c = 0; c < NC; c++)
            vout[(size_t)(b * NC + c) * NV + v] = (c == (int)bc) ? 1.0f : 0.0f;
    }
}

// ---------------- launcher ----------------
extern "C" void kernel_launch(void* const* d_in, const int* in_sizes, int n_in,
                              void* d_out, int out_size) {
    const float* v0 = (const float*)d_in[0];
    const float* W  = (const float*)d_in[1];
    const float* bb = (const float*)d_in[2];
    const float* cc = (const float*)d_in[3];
    (void)in_sizes; (void)n_in; (void)out_size;

    float* out    = (float*)d_out;
    float* out_v  = out;                     // (B,C,V,1)
    float* out_h  = out + (size_t)NBCV;      // (B,H,1)
    float* out_h0 = out_h + (size_t)NBH;     // (B,H,1)

    // keys = jax.random.split(jax.random.key(42), 5)
    uint32_t keys[5][2];
#if JAX_PARTITIONABLE
    for (uint32_t i = 0; i < 5; i++)
        threefry(0u, 42u, 0u, i, keys[i][0], keys[i][1]);
#else
    uint32_t o0[5], o1[5];
    for (uint32_t i = 0; i < 5; i++)
        threefry(0u, 42u, i, i + 5u, o0[i], o1[i]);
    uint32_t bits[10] = {o0[0], o0[1], o0[2], o0[3], o0[4],
                         o1[0], o1[1], o1[2], o1[3], o1[4]};
    for (int j = 0; j < 5; j++) { keys[j][0] = bits[2*j]; keys[j][1] = bits[2*j+1]; }
#endif

    dim3 ggrid(NCV / 128, NB / 128);

    k_transpose  <<<NC * NV * NH / 256, 256>>>(W);
    k_extract_idx<<<NB * NV / 256, 256>>>(v0);
    // h = sample_h(keys[0], v0)  -> h_given_v0
    k_sample_h   <<<NB / BT, 256>>>(keys[0][0], keys[0][1], cc, out_h0);
    // iter 0
    k_gemm       <<<ggrid, 256>>>();
    k_categorical<<<NB * NV / 256, 256>>>(keys[1][0], keys[1][1], bb, nullptr, 0);
    k_sample_h   <<<NB / BT, 256>>>(keys[2][0], keys[2][1], cc, nullptr);
    // iter 1
    k_gemm       <<<ggrid, 256>>>();
    k_categorical<<<NB * NV / 256, 256>>>(keys[3][0], keys[3][1], bb, out_v, 1);
    k_sample_h   <<<NB / BT, 256>>>(keys[4][0], keys[4][1], cc, out_h);
}

// round 4
// speedup vs baseline: 2.1071x; 2.1071x over previous
#include <cuda_runtime.h>
#include <cuda_bf16.h>
#include <cstdint>
#include <math.h>

// Problem constants
#define NB 16384
#define NC 5
#define NH 256
#define NV 512
#define NCV 2560
#define NBH 4194304
#define NBCV 41943040u
#define TINYF 1.17549435082228751e-38f

// ---------------- scratch (static device globals) ----------------
__device__ __nv_bfloat16 g_A[(size_t)NB * NCV];     // one-hot v bf16 (A for sample_h, K=2560)
__device__ __nv_bfloat16 g_hb[(size_t)NB * NH];     // h bf16 (A for sample_v, K=256)
__device__ float         g_logits[(size_t)NB * NCV];
__device__ __nv_bfloat16 g_Wt3[3][NCV * NH];        // [split][cv][h]  (B for sample_v)
__device__ __nv_bfloat16 g_Wh3[3][NH * NCV];        // [split][h][cv]  (B for sample_h)

// ---------------- threefry2x32 (bit-exact with JAX, partitionable) ----------------
__host__ __device__ __forceinline__ uint32_t rotl32(uint32_t x, int r) {
#ifdef __CUDA_ARCH__
    return __funnelshift_l(x, x, r);
#else
    return (x << r) | (x >> (32 - r));
#endif
}

__host__ __device__ inline void threefry(uint32_t k0, uint32_t k1,
                                         uint32_t x0, uint32_t x1,
                                         uint32_t& o0, uint32_t& o1) {
    uint32_t k2 = k0 ^ k1 ^ 0x1BD11BDAu;
#define TFR(r) { x0 += x1; x1 = rotl32(x1, (r)); x1 ^= x0; }
    x0 += k0; x1 += k1;
    TFR(13) TFR(15) TFR(26) TFR(6)   x0 += k1; x1 += k2 + 1u;
    TFR(17) TFR(29) TFR(16) TFR(24)  x0 += k2; x1 += k0 + 2u;
    TFR(13) TFR(15) TFR(26) TFR(6)   x0 += k0; x1 += k1 + 3u;
    TFR(17) TFR(29) TFR(16) TFR(24)  x0 += k1; x1 += k2 + 4u;
    TFR(13) TFR(15) TFR(26) TFR(6)   x0 += k2; x1 += k0 + 5u;
#undef TFR
    o0 = x0; o1 = x1;
}

__device__ __forceinline__ uint32_t rand_bits(uint32_t k0, uint32_t k1, uint32_t i) {
    uint32_t a, b;
    threefry(k0, k1, 0u, i, a, b);
    return a ^ b;
}

__device__ __forceinline__ float bits_to_unit(uint32_t bits) {
    return __fadd_rn(__uint_as_float((bits >> 9) | 0x3f800000u), -1.0f);
}

// ---------------- small helpers ----------------
__device__ __forceinline__ uint32_t smem_u32(const void* p) {
    uint32_t a;
    asm("{ .reg .u64 t; cvta.to.shared.u64 t, %1; cvt.u32.u64 %0, t; }" : "=r"(a) : "l"(p));
    return a;
}

__device__ __forceinline__ void cp16(uint32_t s, const void* g) {
    asm volatile("cp.async.cg.shared.global [%0], [%1], 16;" :: "r"(s), "l"(g));
}
#define CP_COMMIT() asm volatile("cp.async.commit_group;" ::: "memory")
#define CP_WAIT0()  asm volatile("cp.async.wait_group 0;" ::: "memory")

__device__ __forceinline__ void ldmx4(uint32_t* r, uint32_t addr) {
    asm volatile("ldmatrix.sync.aligned.m8n8.x4.shared.b16 {%0,%1,%2,%3}, [%4];"
                 : "=r"(r[0]), "=r"(r[1]), "=r"(r[2]), "=r"(r[3]) : "r"(addr));
}

__device__ __forceinline__ void mma16816(float* c, const uint32_t* a,
                                         uint32_t b0, uint32_t b1) {
    asm volatile(
        "mma.sync.aligned.m16n8k16.row.col.f32.bf16.bf16.f32 "
        "{%0,%1,%2,%3}, {%4,%5,%6,%7}, {%8,%9}, {%0,%1,%2,%3};"
        : "+f"(c[0]), "+f"(c[1]), "+f"(c[2]), "+f"(c[3])
        : "r"(a[0]), "r"(a[1]), "r"(a[2]), "r"(a[3]), "r"(b0), "r"(b1));
}

// ---------------- prep kernels ----------------
__device__ __forceinline__ void split3(float w, __nv_bfloat16& a, __nv_bfloat16& b,
                                       __nv_bfloat16& c) {
    a = __float2bfloat16(w);
    float r1 = w - __bfloat162float(a);
    b = __float2bfloat16(r1);
    float r2 = r1 - __bfloat162float(b);
    c = __float2bfloat16(r2);
}

__global__ void k_prep_wt(const float* __restrict__ W) {
    int i = blockIdx.x * 256 + threadIdx.x;   // over NCV*NH
    int h = i & (NH - 1);
    int cv = i >> 8;
    int v = cv & (NV - 1);
    int c = cv >> 9;
    __nv_bfloat16 a, b, d;
    split3(W[((size_t)(c * NH + h)) * NV + v], a, b, d);
    g_Wt3[0][i] = a; g_Wt3[1][i] = b; g_Wt3[2][i] = d;
}

__global__ void k_prep_wh(const float* __restrict__ W) {
    int cv = blockIdx.x * 256 + threadIdx.x;  // 0..2559
    int h  = blockIdx.y;
    int v = cv & (NV - 1);
    int c = cv >> 9;
    __nv_bfloat16 a, b, d;
    split3(W[((size_t)(c * NH + h)) * NV + v], a, b, d);
    size_t o = (size_t)h * NCV + cv;
    g_Wh3[0][o] = a; g_Wh3[1][o] = b; g_Wh3[2][o] = d;
}

__global__ void k_cast_A0(const float* __restrict__ v0) {
    size_t i = ((size_t)blockIdx.x * 256 + threadIdx.x) * 4;
    float4 f = *(const float4*)(v0 + i);
    __nv_bfloat16 o[4] = {__float2bfloat16(f.x), __float2bfloat16(f.y),
                          __float2bfloat16(f.z), __float2bfloat16(f.w)};
    *(uint2*)(g_A + i) = *(uint2*)o;
}

// ---------------- warp-MMA GEMM: D[128,64] += A[128,K] * sum_s Bs[64,K]^T ----------------
// EPI 0: store logits fp32.  EPI 1: bernoulli-h epilogue (sigmoid + threefry).
#define BM 128
#define BN 64
#define BK 32
#define ROWB 80                       // 32 bf16 (64B) + 16B pad -> conflict-free ldmatrix
#define ATILE (BM * ROWB)             // 10240
#define BTILE (BN * ROWB)             // 5120
#define STG (ATILE + 3 * BTILE)       // 25600
#define SMEMB (2 * STG)               // 51200
#define BSPLIT ((size_t)NCV * NH)

template<int EPI>
__global__ __launch_bounds__(256, 2)
void k_mma(const __nv_bfloat16* __restrict__ Asrc, int lda,
           const __nv_bfloat16* __restrict__ Bsrc, int ldb, int nk,
           uint32_t key0, uint32_t key1,
           const float* __restrict__ cvec,
           float* __restrict__ fout) {
    extern __shared__ char smem[];
    const uint32_t sb = smem_u32(smem);
    const int tid = threadIdx.x;
    const int lane = tid & 31;
    const int wid = tid >> 5;
    const int wm = wid & 3;            // 4 warps along M (32 rows each)
    const int wn = wid >> 2;           // 2 warps along N (32 cols each)
    const int bn = blockIdx.x * BN;
    const int bm = blockIdx.y * BM;

    // per-thread global/smem load mapping
    const int ar0 = tid >> 2;          // A rows: ar0, ar0+64
    const int ac  = (tid & 3) * 16;    // smem byte chunk
    const int ack = (tid & 3) * 8;     // gmem k-element offset
    const int br  = tid >> 2;          // B row 0..63

    auto issue = [&](int st, int kc) {
        const int k0 = kc * BK;
        uint32_t s = sb + st * STG;
        cp16(s + ar0 * ROWB + ac,
             Asrc + (size_t)(bm + ar0) * lda + k0 + ack);
        cp16(s + (ar0 + 64) * ROWB + ac,
             Asrc + (size_t)(bm + ar0 + 64) * lda + k0 + ack);
#pragma unroll
        for (int sp = 0; sp < 3; sp++)
            cp16(s + ATILE + sp * BTILE + br * ROWB + ac,
                 Bsrc + sp * BSPLIT + (size_t)(bn + br) * ldb + k0 + ack);
    };

    float acc[2][4][4];
#pragma unroll
    for (int i = 0; i < 2; i++)
#pragma unroll
        for (int j = 0; j < 4; j++)
#pragma unroll
            for (int q = 0; q < 4; q++) acc[i][j][q] = 0.0f;

    issue(0, 0);
    CP_COMMIT();

#pragma unroll 1
    for (int kc = 0; kc < nk; kc++) {
        CP_WAIT0();
        __syncthreads();
        if (kc + 1 < nk) { issue((kc + 1) & 1, kc + 1); CP_COMMIT(); }

        const uint32_t sA = sb + (kc & 1) * STG;
        const uint32_t sB = sA + ATILE;
#pragma unroll
        for (int ks = 0; ks < 2; ks++) {        // two k16 steps per chunk
            uint32_t a[2][4];
#pragma unroll
            for (int mi = 0; mi < 2; mi++)
                ldmx4(a[mi], sA + (uint32_t)((wm * 32 + mi * 16 + (lane & 15)) * ROWB
                                             + ((ks << 1) + (lane >> 4)) * 16));
#pragma unroll
            for (int sp = 0; sp < 3; sp++) {
#pragma unroll
                for (int nh = 0; nh < 2; nh++) { // each covers n-frags 2nh, 2nh+1
                    uint32_t b[4];
                    ldmx4(b, sB + sp * BTILE
                             + (uint32_t)((wn * 32 + nh * 16 + (lane & 7) + ((lane >> 4) << 3)) * ROWB
                                          + ((ks << 1) + ((lane >> 3) & 1)) * 16));
#pragma unroll
                    for (int mi = 0; mi < 2; mi++) {
                        mma16816(acc[mi][nh * 2 + 0], a[mi], b[0], b[1]);
                        mma16816(acc[mi][nh * 2 + 1], a[mi], b[2], b[3]);
                    }
                }
            }
        }
    }

    // ---------------- epilogue ----------------
    const int r4 = lane >> 2;
    const int c2 = (lane & 3) * 2;
#pragma unroll
    for (int mi = 0; mi < 2; mi++) {
#pragma unroll
        for (int ni = 0; ni < 4; ni++) {
            const float* c = acc[mi][ni];
            const int col = bn + wn * 32 + ni * 8 + c2;
            const int row = bm + wm * 32 + mi * 16 + r4;
            if (EPI == 0) {
                *(float2*)(fout + (size_t)row * NCV + col)       = make_float2(c[0], c[1]);
                *(float2*)(fout + (size_t)(row + 8) * NCV + col) = make_float2(c[2], c[3]);
            } else {
                const float cv0 = cvec[col], cv1 = cvec[col + 1];
#pragma unroll
                for (int half = 0; half < 2; half++) {
                    const int rr = row + half * 8;
                    float x0 = __fadd_rn(c[half * 2 + 0], cv0);
                    float x1 = __fadd_rn(c[half * 2 + 1], cv1);
                    float p0 = __fadd_rn(__fmul_rn(0.5f, tanhf(__fmul_rn(0.5f, x0))), 0.5f);
                    float p1 = __fadd_rn(__fmul_rn(0.5f, tanhf(__fmul_rn(0.5f, x1))), 0.5f);
                    uint32_t gi = (uint32_t)rr * NH + col;
                    float u0 = bits_to_unit(rand_bits(key0, key1, gi));
                    float u1 = bits_to_unit(rand_bits(key0, key1, gi + 1));
                    uint32_t b0 = (u0 < p0) ? 0x3F80u : 0u;
                    uint32_t b1 = (u1 < p1) ? 0x3F80u : 0u;
                    *(uint32_t*)(g_hb + (size_t)rr * NH + col) = (b1 << 16) | b0;
                    if (fout)
                        *(float2*)(fout + (size_t)rr * NH + col) =
                            make_float2(b0 ? 1.0f : 0.0f, b1 ? 1.0f : 0.0f);
                }
            }
        }
    }
}

// ---------------- categorical (gumbel-argmax); writes bf16 one-hot into g_A ----------------
__global__ void k_categorical(uint32_t k0, uint32_t k1,
                              const float* __restrict__ bvec,
                              float* __restrict__ vout, int write_out) {
    int i = blockIdx.x * 256 + threadIdx.x;   // over B*V
    int b = i >> 9;
    int v = i & (NV - 1);

    float best = 0.0f;
    uint32_t bc = 0;
#pragma unroll
    for (int c = 0; c < NC; c++) {
        float l = __fadd_rn(g_logits[(size_t)b * NCV + c * NV + v], bvec[c * NV + v]);
        uint32_t gi = ((uint32_t)b * NC + c) * NV + v;
        float u = bits_to_unit(rand_bits(k0, k1, gi));
        float up = fmaxf(__fadd_rn(u, TINYF), TINYF);
        float gmb = -logf(-logf(up));
        float s = __fadd_rn(gmb, l);
        if (c == 0 || s > best) { best = s; bc = (uint32_t)c; }
    }
#pragma unroll
    for (int c = 0; c < NC; c++)
        g_A[(size_t)b * NCV + c * NV + v] =
            __float2bfloat16((c == (int)bc) ? 1.0f : 0.0f);
    if (write_out) {
#pragma unroll
        for (int c = 0; c < NC; c++)
            vout[(size_t)(b * NC + c) * NV + v] = (c == (int)bc) ? 1.0f : 0.0f;
    }
}

// ---------------- launcher ----------------
extern "C" void kernel_launch(void* const* d_in, const int* in_sizes, int n_in,
                              void* d_out, int out_size) {
    const float* v0 = (const float*)d_in[0];
    const float* W  = (const float*)d_in[1];
    const float* bb = (const float*)d_in[2];
    const float* cc = (const float*)d_in[3];
    (void)in_sizes; (void)n_in; (void)out_size;

    float* out    = (float*)d_out;
    float* out_v  = out;
    float* out_h  = out + (size_t)NBCV;
    float* out_h0 = out_h + (size_t)NBH;

    // keys = jax.random.split(jax.random.key(42), 5)  (partitionable)
    uint32_t keys[5][2];
    for (uint32_t i = 0; i < 5; i++)
        threefry(0u, 42u, 0u, i, keys[i][0], keys[i][1]);

    cudaFuncSetAttribute(k_mma<0>, cudaFuncAttributeMaxDynamicSharedMemorySize, SMEMB);
    cudaFuncSetAttribute(k_mma<1>, cudaFuncAttributeMaxDynamicSharedMemorySize, SMEMB);

    void *pA, *pHB, *pWt, *pWh, *pLog;
    cudaGetSymbolAddress(&pA, g_A);
    cudaGetSymbolAddress(&pHB, g_hb);
    cudaGetSymbolAddress(&pWt, g_Wt3);
    cudaGetSymbolAddress(&pWh, g_Wh3);
    cudaGetSymbolAddress(&pLog, g_logits);
    const __nv_bfloat16* A   = (const __nv_bfloat16*)pA;
    const __nv_bfloat16* HB  = (const __nv_bfloat16*)pHB;
    const __nv_bfloat16* Wt3 = (const __nv_bfloat16*)pWt;
    const __nv_bfloat16* Wh3 = (const __nv_bfloat16*)pWh;
    float* LOG = (float*)pLog;

    dim3 gh(NH / BN, NB / BM);     // (4, 128)  sample_h GEMM
    dim3 gv(NCV / BN, NB / BM);    // (40, 128) sample_v GEMM

    k_prep_wt<<<NCV * NH / 256, 256>>>(W);
    k_prep_wh<<<dim3(NCV / 256, NH), 256>>>(W);
    k_cast_A0<<<NBCV / 1024, 256>>>(v0);

    // h = sample_h(keys[0], v0) -> out_h0
    k_mma<1><<<gh, 256, SMEMB>>>(A, NCV, Wh3, NCV, NCV / BK,
                                 keys[0][0], keys[0][1], cc, out_h0);
    // iter 0
    k_mma<0><<<gv, 256, SMEMB>>>(HB, NH, Wt3, NH, NH / BK, 0, 0, nullptr, LOG);
    k_categorical<<<NB * NV / 256, 256>>>(keys[1][0], keys[1][1], bb, nullptr, 0);
    k_mma<1><<<gh, 256, SMEMB>>>(A, NCV, Wh3, NCV, NCV / BK,
                                 keys[2][0], keys[2][1], cc, nullptr);
    // iter 1
    k_mma<0><<<gv, 256, SMEMB>>>(HB, NH, Wt3, NH, NH / BK, 0, 0, nullptr, LOG);
    k_categorical<<<NB * NV / 256, 256>>>(keys[3][0], keys[3][1], bb, out_v, 1);
    k_mma<1><<<gh, 256, SMEMB>>>(A, NCV, Wh3, NCV, NCV / BK,
                                 keys[4][0], keys[4][1], cc, out_h);
}

// round 5
// speedup vs baseline: 2.1302x; 1.0110x over previous
#include <cuda_runtime.h>
#include <cuda_bf16.h>
#include <cstdint>
#include <math.h>

// Problem constants
#define NB 16384
#define NC 5
#define NH 256
#define NV 512
#define NCV 2560
#define NBH 4194304
#define NBCV 41943040u
#define TINYF 1.17549435082228751e-38f

// ---------------- scratch (static device globals) ----------------
__device__ __nv_bfloat16 g_A[(size_t)NB * NCV];     // one-hot v bf16 (A for sample_h, K=2560)
__device__ __nv_bfloat16 g_hb[(size_t)NB * NH];     // h bf16 (A for sample_v, K=256)
__device__ float         g_logits[(size_t)NB * NCV];
__device__ __nv_bfloat16 g_Wt3[3][NCV * NH];        // [split][cv][h]  (B for sample_v)
__device__ __nv_bfloat16 g_Wh3[3][NH * NCV];        // [split][h][cv]  (B for sample_h)

// ---------------- threefry2x32 (bit-exact with JAX, partitionable) ----------------
__host__ __device__ __forceinline__ uint32_t rotl32(uint32_t x, int r) {
#ifdef __CUDA_ARCH__
    return __funnelshift_l(x, x, r);
#else
    return (x << r) | (x >> (32 - r));
#endif
}

__host__ __device__ inline void threefry(uint32_t k0, uint32_t k1,
                                         uint32_t x0, uint32_t x1,
                                         uint32_t& o0, uint32_t& o1) {
    uint32_t k2 = k0 ^ k1 ^ 0x1BD11BDAu;
#define TFR(r) { x0 += x1; x1 = rotl32(x1, (r)); x1 ^= x0; }
    x0 += k0; x1 += k1;
    TFR(13) TFR(15) TFR(26) TFR(6)   x0 += k1; x1 += k2 + 1u;
    TFR(17) TFR(29) TFR(16) TFR(24)  x0 += k2; x1 += k0 + 2u;
    TFR(13) TFR(15) TFR(26) TFR(6)   x0 += k0; x1 += k1 + 3u;
    TFR(17) TFR(29) TFR(16) TFR(24)  x0 += k1; x1 += k2 + 4u;
    TFR(13) TFR(15) TFR(26) TFR(6)   x0 += k2; x1 += k0 + 5u;
#undef TFR
    o0 = x0; o1 = x1;
}

__device__ __forceinline__ uint32_t rand_bits(uint32_t k0, uint32_t k1, uint32_t i) {
    uint32_t a, b;
    threefry(k0, k1, 0u, i, a, b);
    return a ^ b;
}

__device__ __forceinline__ float bits_to_unit(uint32_t bits) {
    return __fadd_rn(__uint_as_float((bits >> 9) | 0x3f800000u), -1.0f);
}

// ---------------- small helpers ----------------
__device__ __forceinline__ uint32_t smem_u32(const void* p) {
    uint32_t a;
    asm("{ .reg .u64 t; cvta.to.shared.u64 t, %1; cvt.u32.u64 %0, t; }" : "=r"(a) : "l"(p));
    return a;
}

__device__ __forceinline__ void cp16(uint32_t s, const void* g) {
    asm volatile("cp.async.cg.shared.global [%0], [%1], 16;" :: "r"(s), "l"(g));
}
#define CP_COMMIT() asm volatile("cp.async.commit_group;" ::: "memory")
#define CP_WAIT(n)  asm volatile("cp.async.wait_group %0;" :: "n"(n) : "memory")

__device__ __forceinline__ void ldmx4(uint32_t* r, uint32_t addr) {
    asm volatile("ldmatrix.sync.aligned.m8n8.x4.shared.b16 {%0,%1,%2,%3}, [%4];"
                 : "=r"(r[0]), "=r"(r[1]), "=r"(r[2]), "=r"(r[3]) : "r"(addr));
}

__device__ __forceinline__ void mma16816(float* c, const uint32_t* a,
                                         uint32_t b0, uint32_t b1) {
    asm volatile(
        "mma.sync.aligned.m16n8k16.row.col.f32.bf16.bf16.f32 "
        "{%0,%1,%2,%3}, {%4,%5,%6,%7}, {%8,%9}, {%0,%1,%2,%3};"
        : "+f"(c[0]), "+f"(c[1]), "+f"(c[2]), "+f"(c[3])
        : "r"(a[0]), "r"(a[1]), "r"(a[2]), "r"(a[3]), "r"(b0), "r"(b1));
}

// ---------------- prep kernels ----------------
__device__ __forceinline__ void split3(float w, __nv_bfloat16& a, __nv_bfloat16& b,
                                       __nv_bfloat16& c) {
    a = __float2bfloat16(w);
    float r1 = w - __bfloat162float(a);
    b = __float2bfloat16(r1);
    float r2 = r1 - __bfloat162float(b);
    c = __float2bfloat16(r2);
}

__global__ void k_prep_wt(const float* __restrict__ W) {
    int i = blockIdx.x * 256 + threadIdx.x;   // over NCV*NH
    int h = i & (NH - 1);
    int cv = i >> 8;
    int v = cv & (NV - 1);
    int c = cv >> 9;
    __nv_bfloat16 a, b, d;
    split3(W[((size_t)(c * NH + h)) * NV + v], a, b, d);
    g_Wt3[0][i] = a; g_Wt3[1][i] = b; g_Wt3[2][i] = d;
}

__global__ void k_prep_wh(const float* __restrict__ W) {
    int cv = blockIdx.x * 256 + threadIdx.x;  // 0..2559
    int h  = blockIdx.y;
    int v = cv & (NV - 1);
    int c = cv >> 9;
    __nv_bfloat16 a, b, d;
    split3(W[((size_t)(c * NH + h)) * NV + v], a, b, d);
    size_t o = (size_t)h * NCV + cv;
    g_Wh3[0][o] = a; g_Wh3[1][o] = b; g_Wh3[2][o] = d;
}

__global__ void k_cast_A0(const float* __restrict__ v0) {
    size_t i = ((size_t)blockIdx.x * 256 + threadIdx.x) * 4;
    float4 f = *(const float4*)(v0 + i);
    __nv_bfloat16 o[4] = {__float2bfloat16(f.x), __float2bfloat16(f.y),
                          __float2bfloat16(f.z), __float2bfloat16(f.w)};
    *(uint2*)(g_A + i) = *(uint2*)o;
}

// ---------------- warp-MMA GEMM: D[128,64] += A[128,K] * sum_s Bs[64,K]^T ----------------
// EPI 0: store logits fp32.  EPI 1: bernoulli-h epilogue (sigmoid + threefry).
#define BM 128
#define BN 64
#define BK 32
#define ROWB 80                       // 32 bf16 (64B) + 16B pad -> conflict-free ldmatrix
#define ATILE (BM * ROWB)             // 10240
#define BTILE (BN * ROWB)             // 5120
#define STG (ATILE + 3 * BTILE)       // 25600 bytes per stage
#define NSTAGE 4
#define SMEMB (NSTAGE * STG)          // 102400
#define BSPLIT ((size_t)NCV * NH)

template<int EPI>
__global__ __launch_bounds__(256, 2)
void k_mma(const __nv_bfloat16* __restrict__ Asrc, int lda,
           const __nv_bfloat16* __restrict__ Bsrc, int ldb, int nk,
           uint32_t key0, uint32_t key1,
           const float* __restrict__ cvec,
           float* __restrict__ fout) {
    extern __shared__ char smem[];
    const uint32_t sb = smem_u32(smem);
    const int tid = threadIdx.x;
    const int lane = tid & 31;
    const int wid = tid >> 5;
    const int wm = wid & 3;            // 4 warps along M (32 rows each)
    const int wn = wid >> 2;           // 2 warps along N (32 cols each)
    const int bn = blockIdx.x * BN;
    const int bm = blockIdx.y * BM;

    // per-thread global/smem load mapping
    const int ar0 = tid >> 2;          // A rows: ar0, ar0+64
    const int ac  = (tid & 3) * 16;    // smem byte chunk
    const int ack = (tid & 3) * 8;     // gmem k-element offset
    const int br  = tid >> 2;          // B row 0..63

    auto issue = [&](int kc) {
        const int k0 = kc * BK;
        uint32_t s = sb + (kc & (NSTAGE - 1)) * STG;
        cp16(s + ar0 * ROWB + ac,
             Asrc + (size_t)(bm + ar0) * lda + k0 + ack);
        cp16(s + (ar0 + 64) * ROWB + ac,
             Asrc + (size_t)(bm + ar0 + 64) * lda + k0 + ack);
#pragma unroll
        for (int sp = 0; sp < 3; sp++)
            cp16(s + ATILE + sp * BTILE + br * ROWB + ac,
                 Bsrc + sp * BSPLIT + (size_t)(bn + br) * ldb + k0 + ack);
    };

    float acc[2][4][4];
#pragma unroll
    for (int i = 0; i < 2; i++)
#pragma unroll
        for (int j = 0; j < 4; j++)
#pragma unroll
            for (int q = 0; q < 4; q++) acc[i][j][q] = 0.0f;

    // prologue: fill NSTAGE-1 stages
    issue(0); CP_COMMIT();
    issue(1); CP_COMMIT();
    issue(2); CP_COMMIT();

#pragma unroll 1
    for (int kc = 0; kc < nk; kc++) {
        CP_WAIT(2);                    // stage kc complete (<=2 groups pending)
        __syncthreads();
        // keep commit cadence constant (empty groups near the tail)
        if (kc + 3 < nk) issue(kc + 3);
        CP_COMMIT();

        const uint32_t sA = sb + (kc & (NSTAGE - 1)) * STG;
        const uint32_t sB = sA + ATILE;
#pragma unroll
        for (int ks = 0; ks < 2; ks++) {        // two k16 steps per chunk
            uint32_t a[2][4];
#pragma unroll
            for (int mi = 0; mi < 2; mi++)
                ldmx4(a[mi], sA + (uint32_t)((wm * 32 + mi * 16 + (lane & 15)) * ROWB
                                             + ((ks << 1) + (lane >> 4)) * 16));
#pragma unroll
            for (int sp = 0; sp < 3; sp++) {
#pragma unroll
                for (int nh = 0; nh < 2; nh++) { // each covers n-frags 2nh, 2nh+1
                    uint32_t b[4];
                    ldmx4(b, sB + sp * BTILE
                             + (uint32_t)((wn * 32 + nh * 16 + (lane & 7) + ((lane >> 4) << 3)) * ROWB
                                          + ((ks << 1) + ((lane >> 3) & 1)) * 16));
#pragma unroll
                    for (int mi = 0; mi < 2; mi++) {
                        mma16816(acc[mi][nh * 2 + 0], a[mi], b[0], b[1]);
                        mma16816(acc[mi][nh * 2 + 1], a[mi], b[2], b[3]);
                    }
                }
            }
        }
    }

    // ---------------- epilogue ----------------
    const int r4 = lane >> 2;
    const int c2 = (lane & 3) * 2;
#pragma unroll
    for (int mi = 0; mi < 2; mi++) {
#pragma unroll
        for (int ni = 0; ni < 4; ni++) {
            const float* c = acc[mi][ni];
            const int col = bn + wn * 32 + ni * 8 + c2;
            const int row = bm + wm * 32 + mi * 16 + r4;
            if (EPI == 0) {
                *(float2*)(fout + (size_t)row * NCV + col)       = make_float2(c[0], c[1]);
                *(float2*)(fout + (size_t)(row + 8) * NCV + col) = make_float2(c[2], c[3]);
            } else {
                const float cv0 = cvec[col], cv1 = cvec[col + 1];
#pragma unroll
                for (int half = 0; half < 2; half++) {
                    const int rr = row + half * 8;
                    float x0 = __fadd_rn(c[half * 2 + 0], cv0);
                    float x1 = __fadd_rn(c[half * 2 + 1], cv1);
                    float p0 = __fadd_rn(__fmul_rn(0.5f, tanhf(__fmul_rn(0.5f, x0))), 0.5f);
                    float p1 = __fadd_rn(__fmul_rn(0.5f, tanhf(__fmul_rn(0.5f, x1))), 0.5f);
                    uint32_t gi = (uint32_t)rr * NH + col;
                    float u0 = bits_to_unit(rand_bits(key0, key1, gi));
                    float u1 = bits_to_unit(rand_bits(key0, key1, gi + 1));
                    uint32_t b0 = (u0 < p0) ? 0x3F80u : 0u;
                    uint32_t b1 = (u1 < p1) ? 0x3F80u : 0u;
                    *(uint32_t*)(g_hb + (size_t)rr * NH + col) = (b1 << 16) | b0;
                    if (fout)
                        *(float2*)(fout + (size_t)rr * NH + col) =
                            make_float2(b0 ? 1.0f : 0.0f, b1 ? 1.0f : 0.0f);
                }
            }
        }
    }
}

// ---------------- categorical (gumbel-argmax); writes bf16 one-hot into g_A ----------------
__global__ void k_categorical(uint32_t k0, uint32_t k1,
                              const float* __restrict__ bvec,
                              float* __restrict__ vout, int write_out) {
    int i = blockIdx.x * 256 + threadIdx.x;   // over B*V
    int b = i >> 9;
    int v = i & (NV - 1);

    float best = 0.0f;
    uint32_t bc = 0;
#pragma unroll
    for (int c = 0; c < NC; c++) {
        float l = __fadd_rn(g_logits[(size_t)b * NCV + c * NV + v], bvec[c * NV + v]);
        uint32_t gi = ((uint32_t)b * NC + c) * NV + v;
        float u = bits_to_unit(rand_bits(k0, k1, gi));
        float up = fmaxf(__fadd_rn(u, TINYF), TINYF);
        float gmb = -logf(-logf(up));
        float s = __fadd_rn(gmb, l);
        if (c == 0 || s > best) { best = s; bc = (uint32_t)c; }
    }
#pragma unroll
    for (int c = 0; c < NC; c++)
        g_A[(size_t)b * NCV + c * NV + v] =
            __float2bfloat16((c == (int)bc) ? 1.0f : 0.0f);
    if (write_out) {
#pragma unroll
        for (int c = 0; c < NC; c++)
            vout[(size_t)(b * NC + c) * NV + v] = (c == (int)bc) ? 1.0f : 0.0f;
    }
}

// ---------------- launcher ----------------
extern "C" void kernel_launch(void* const* d_in, const int* in_sizes, int n_in,
                              void* d_out, int out_size) {
    const float* v0 = (const float*)d_in[0];
    const float* W  = (const float*)d_in[1];
    const float* bb = (const float*)d_in[2];
    const float* cc = (const float*)d_in[3];
    (void)in_sizes; (void)n_in; (void)out_size;

    float* out    = (float*)d_out;
    float* out_v  = out;
    float* out_h  = out + (size_t)NBCV;
    float* out_h0 = out_h + (size_t)NBH;

    // keys = jax.random.split(jax.random.key(42), 5)  (partitionable)
    uint32_t keys[5][2];
    for (uint32_t i = 0; i < 5; i++)
        threefry(0u, 42u, 0u, i, keys[i][0], keys[i][1]);

    cudaFuncSetAttribute(k_mma<0>, cudaFuncAttributeMaxDynamicSharedMemorySize, SMEMB);
    cudaFuncSetAttribute(k_mma<1>, cudaFuncAttributeMaxDynamicSharedMemorySize, SMEMB);

    void *pA, *pHB, *pWt, *pWh, *pLog;
    cudaGetSymbolAddress(&pA, g_A);
    cudaGetSymbolAddress(&pHB, g_hb);
    cudaGetSymbolAddress(&pWt, g_Wt3);
    cudaGetSymbolAddress(&pWh, g_Wh3);
    cudaGetSymbolAddress(&pLog, g_logits);
    const __nv_bfloat16* A   = (const __nv_bfloat16*)pA;
    const __nv_bfloat16* HB  = (const __nv_bfloat16*)pHB;
    const __nv_bfloat16* Wt3 = (const __nv_bfloat16*)pWt;
    const __nv_bfloat16* Wh3 = (const __nv_bfloat16*)pWh;
    float* LOG = (float*)pLog;

    dim3 gh(NH / BN, NB / BM);     // (4, 128)  sample_h GEMM
    dim3 gv(NCV / BN, NB / BM);    // (40, 128) sample_v GEMM

    k_prep_wt<<<NCV * NH / 256, 256>>>(W);
    k_prep_wh<<<dim3(NCV / 256, NH), 256>>>(W);
    k_cast_A0<<<NBCV / 1024, 256>>>(v0);

    // h = sample_h(keys[0], v0) -> out_h0
    k_mma<1><<<gh, 256, SMEMB>>>(A, NCV, Wh3, NCV, NCV / BK,
                                 keys[0][0], keys[0][1], cc, out_h0);
    // iter 0
    k_mma<0><<<gv, 256, SMEMB>>>(HB, NH, Wt3, NH, NH / BK, 0, 0, nullptr, LOG);
    k_categorical<<<NB * NV / 256, 256>>>(keys[1][0], keys[1][1], bb, nullptr, 0);
    k_mma<1><<<gh, 256, SMEMB>>>(A, NCV, Wh3, NCV, NCV / BK,
                                 keys[2][0], keys[2][1], cc, nullptr);
    // iter 1
    k_mma<0><<<gv, 256, SMEMB>>>(HB, NH, Wt3, NH, NH / BK, 0, 0, nullptr, LOG);
    k_categorical<<<NB * NV / 256, 256>>>(keys[3][0], keys[3][1], bb, out_v, 1);
    k_mma<1><<<gh, 256, SMEMB>>>(A, NCV, Wh3, NCV, NCV / BK,
                                 keys[4][0], keys[4][1], cc, out_h);
}

// round 6
// speedup vs baseline: 2.1429x; 1.0060x over previous
#include <cuda_runtime.h>
#include <cuda_bf16.h>
#include <cstdint>
#include <math.h>

// Problem constants
#define NB 16384
#define NC 5
#define NH 256
#define NV 512
#define NCV 2560
#define NBH 4194304
#define NBCV 41943040u
#define TINYF 1.17549435082228751e-38f

// ---------------- scratch (static device globals) ----------------
__device__ __nv_bfloat16 g_A[(size_t)NB * NCV];     // one-hot v bf16 (A for sample_h, K=2560)
__device__ __nv_bfloat16 g_hb[(size_t)NB * NH];     // h bf16 (A for sample_v, K=256)
__device__ float         g_logits[(size_t)NB * NCV];
__device__ __nv_bfloat16 g_Wt3[3][NCV * NH];        // [split][cv][h]  (B for sample_v)
__device__ __nv_bfloat16 g_Wh3[3][NH * NCV];        // [split][h][cv]  (B for sample_h)

// ---------------- threefry2x32 (bit-exact with JAX, partitionable) ----------------
__host__ __device__ __forceinline__ uint32_t rotl32(uint32_t x, int r) {
#ifdef __CUDA_ARCH__
    return __funnelshift_l(x, x, r);
#else
    return (x << r) | (x >> (32 - r));
#endif
}

__host__ __device__ inline void threefry(uint32_t k0, uint32_t k1,
                                         uint32_t x0, uint32_t x1,
                                         uint32_t& o0, uint32_t& o1) {
    uint32_t k2 = k0 ^ k1 ^ 0x1BD11BDAu;
#define TFR(r) { x0 += x1; x1 = rotl32(x1, (r)); x1 ^= x0; }
    x0 += k0; x1 += k1;
    TFR(13) TFR(15) TFR(26) TFR(6)   x0 += k1; x1 += k2 + 1u;
    TFR(17) TFR(29) TFR(16) TFR(24)  x0 += k2; x1 += k0 + 2u;
    TFR(13) TFR(15) TFR(26) TFR(6)   x0 += k0; x1 += k1 + 3u;
    TFR(17) TFR(29) TFR(16) TFR(24)  x0 += k1; x1 += k2 + 4u;
    TFR(13) TFR(15) TFR(26) TFR(6)   x0 += k2; x1 += k0 + 5u;
#undef TFR
    o0 = x0; o1 = x1;
}

__device__ __forceinline__ uint32_t rand_bits(uint32_t k0, uint32_t k1, uint32_t i) {
    uint32_t a, b;
    threefry(k0, k1, 0u, i, a, b);
    return a ^ b;
}

__device__ __forceinline__ float bits_to_unit(uint32_t bits) {
    return __fadd_rn(__uint_as_float((bits >> 9) | 0x3f800000u), -1.0f);
}

// ---------------- small helpers ----------------
__device__ __forceinline__ uint32_t smem_u32(const void* p) {
    uint32_t a;
    asm("{ .reg .u64 t; cvta.to.shared.u64 t, %1; cvt.u32.u64 %0, t; }" : "=r"(a) : "l"(p));
    return a;
}

__device__ __forceinline__ void cp16(uint32_t s, const void* g) {
    asm volatile("cp.async.cg.shared.global [%0], [%1], 16;" :: "r"(s), "l"(g));
}
#define CP_COMMIT() asm volatile("cp.async.commit_group;" ::: "memory")
#define CP_WAIT(n)  asm volatile("cp.async.wait_group %0;" :: "n"(n) : "memory")

__device__ __forceinline__ void ldmx4(uint32_t* r, uint32_t addr) {
    asm volatile("ldmatrix.sync.aligned.m8n8.x4.shared.b16 {%0,%1,%2,%3}, [%4];"
                 : "=r"(r[0]), "=r"(r[1]), "=r"(r[2]), "=r"(r[3]) : "r"(addr));
}

__device__ __forceinline__ void mma16816(float* c, const uint32_t* a,
                                         uint32_t b0, uint32_t b1) {
    asm volatile(
        "mma.sync.aligned.m16n8k16.row.col.f32.bf16.bf16.f32 "
        "{%0,%1,%2,%3}, {%4,%5,%6,%7}, {%8,%9}, {%0,%1,%2,%3};"
        : "+f"(c[0]), "+f"(c[1]), "+f"(c[2]), "+f"(c[3])
        : "r"(a[0]), "r"(a[1]), "r"(a[2]), "r"(a[3]), "r"(b0), "r"(b1));
}

// ---------------- prep kernels ----------------
__device__ __forceinline__ void split3(float w, __nv_bfloat16& a, __nv_bfloat16& b,
                                       __nv_bfloat16& c) {
    a = __float2bfloat16(w);
    float r1 = w - __bfloat162float(a);
    b = __float2bfloat16(r1);
    float r2 = r1 - __bfloat162float(b);
    c = __float2bfloat16(r2);
}

__global__ void k_prep_wt(const float* __restrict__ W) {
    int i = blockIdx.x * 256 + threadIdx.x;   // over NCV*NH
    int h = i & (NH - 1);
    int cv = i >> 8;
    int v = cv & (NV - 1);
    int c = cv >> 9;
    __nv_bfloat16 a, b, d;
    split3(W[((size_t)(c * NH + h)) * NV + v], a, b, d);
    g_Wt3[0][i] = a; g_Wt3[1][i] = b; g_Wt3[2][i] = d;
}

__global__ void k_prep_wh(const float* __restrict__ W) {
    int cv = blockIdx.x * 256 + threadIdx.x;  // 0..2559
    int h  = blockIdx.y;
    int v = cv & (NV - 1);
    int c = cv >> 9;
    __nv_bfloat16 a, b, d;
    split3(W[((size_t)(c * NH + h)) * NV + v], a, b, d);
    size_t o = (size_t)h * NCV + cv;
    g_Wh3[0][o] = a; g_Wh3[1][o] = b; g_Wh3[2][o] = d;
}

__global__ void k_cast_A0(const float* __restrict__ v0) {
    size_t i = ((size_t)blockIdx.x * 256 + threadIdx.x) * 4;
    float4 f = *(const float4*)(v0 + i);
    __nv_bfloat16 o[4] = {__float2bfloat16(f.x), __float2bfloat16(f.y),
                          __float2bfloat16(f.z), __float2bfloat16(f.w)};
    *(uint2*)(g_A + i) = *(uint2*)o;
}

// ---------------- warp-MMA GEMM: D[128,64] += A[128,K] * sum_s Bs[64,K]^T ----------------
// EPI 0: store logits fp32.  EPI 1: bernoulli-h epilogue (sigmoid + threefry).
#define BM 128
#define BN 64
#define BK 32
#define ROWB 80                       // 32 bf16 (64B) + 16B pad -> conflict-free ldmatrix
#define ATILE (BM * ROWB)             // 10240
#define BTILE (BN * ROWB)             // 5120
#define STG (ATILE + 3 * BTILE)       // 25600 bytes per stage
#define NSTAGE 4
#define SMEMB (NSTAGE * STG)          // 102400
#define BSPLIT ((size_t)NCV * NH)

template<int EPI>
__global__ __launch_bounds__(256, 2)
void k_mma(const __nv_bfloat16* __restrict__ Asrc, int lda,
           const __nv_bfloat16* __restrict__ Bsrc, int ldb, int nk,
           uint32_t key0, uint32_t key1,
           const float* __restrict__ cvec,
           float* __restrict__ fout) {
    extern __shared__ char smem[];
    const uint32_t sb = smem_u32(smem);
    const int tid = threadIdx.x;
    const int lane = tid & 31;
    const int wid = tid >> 5;
    const int wm = wid & 3;            // 4 warps along M (32 rows each)
    const int wn = wid >> 2;           // 2 warps along N (32 cols each)
    const int bn = blockIdx.x * BN;
    const int bm = blockIdx.y * BM;

    // per-thread global/smem load mapping
    const int ar0 = tid >> 2;          // A rows: ar0, ar0+64
    const int ac  = (tid & 3) * 16;    // smem byte chunk
    const int ack = (tid & 3) * 8;     // gmem k-element offset
    const int br  = tid >> 2;          // B row 0..63

    // precomputed ldmatrix intra-tile offsets
    const uint32_t aoff = (uint32_t)((wm * 32 + (lane & 15)) * ROWB + (lane >> 4) * 16);
    const uint32_t boff = (uint32_t)((wn * 32 + (lane & 7) + ((lane >> 4) << 3)) * ROWB
                                     + ((lane >> 3) & 1) * 16);

    auto issue = [&](int kc) {
        const int k0 = kc * BK;
        uint32_t s = sb + (kc & (NSTAGE - 1)) * STG;
        cp16(s + ar0 * ROWB + ac,
             Asrc + (size_t)(bm + ar0) * lda + k0 + ack);
        cp16(s + (ar0 + 64) * ROWB + ac,
             Asrc + (size_t)(bm + ar0 + 64) * lda + k0 + ack);
#pragma unroll
        for (int sp = 0; sp < 3; sp++)
            cp16(s + ATILE + sp * BTILE + br * ROWB + ac,
                 Bsrc + sp * BSPLIT + (size_t)(bn + br) * ldb + k0 + ack);
    };

    float acc[2][4][4];
#pragma unroll
    for (int i = 0; i < 2; i++)
#pragma unroll
        for (int j = 0; j < 4; j++)
#pragma unroll
            for (int q = 0; q < 4; q++) acc[i][j][q] = 0.0f;

    // prologue: fill NSTAGE-1 stages
    issue(0); CP_COMMIT();
    issue(1); CP_COMMIT();
    issue(2); CP_COMMIT();

#pragma unroll 1
    for (int kc = 0; kc < nk; kc++) {
        CP_WAIT(2);                    // stage kc complete (<=2 groups pending)
        __syncthreads();
        // keep commit cadence constant (empty groups near the tail)
        if (kc + 3 < nk) issue(kc + 3);
        CP_COMMIT();

        const uint32_t sA = sb + (kc & (NSTAGE - 1)) * STG;
        const uint32_t sB = sA + ATILE;

        // ---- load ALL fragments for both k16 steps up front (16 LDSM) ----
        uint32_t a[2][2][4];           // [ks][mi]
        uint32_t b[2][3][2][4];        // [ks][sp][nh]
#pragma unroll
        for (int ks = 0; ks < 2; ks++) {
#pragma unroll
            for (int mi = 0; mi < 2; mi++)
                ldmx4(a[ks][mi], sA + aoff + (uint32_t)(mi * 16 * ROWB + ks * 32));
#pragma unroll
            for (int sp = 0; sp < 3; sp++)
#pragma unroll
                for (int nh = 0; nh < 2; nh++)
                    ldmx4(b[ks][sp][nh], sB + sp * BTILE + boff
                                         + (uint32_t)(nh * 16 * ROWB + ks * 32));
        }

        // ---- 48 back-to-back MMAs (same per-accumulator order as before) ----
#pragma unroll
        for (int ks = 0; ks < 2; ks++)
#pragma unroll
            for (int sp = 0; sp < 3; sp++)
#pragma unroll
                for (int nh = 0; nh < 2; nh++)
#pragma unroll
                    for (int mi = 0; mi < 2; mi++) {
                        mma16816(acc[mi][nh * 2 + 0], a[ks][mi],
                                 b[ks][sp][nh][0], b[ks][sp][nh][1]);
                        mma16816(acc[mi][nh * 2 + 1], a[ks][mi],
                                 b[ks][sp][nh][2], b[ks][sp][nh][3]);
                    }
    }

    // ---------------- epilogue ----------------
    const int r4 = lane >> 2;
    const int c2 = (lane & 3) * 2;
#pragma unroll
    for (int mi = 0; mi < 2; mi++) {
#pragma unroll
        for (int ni = 0; ni < 4; ni++) {
            const float* c = acc[mi][ni];
            const int col = bn + wn * 32 + ni * 8 + c2;
            const int row = bm + wm * 32 + mi * 16 + r4;
            if (EPI == 0) {
                *(float2*)(fout + (size_t)row * NCV + col)       = make_float2(c[0], c[1]);
                *(float2*)(fout + (size_t)(row + 8) * NCV + col) = make_float2(c[2], c[3]);
            } else {
                const float cv0 = cvec[col], cv1 = cvec[col + 1];
#pragma unroll
                for (int half = 0; half < 2; half++) {
                    const int rr = row + half * 8;
                    float x0 = __fadd_rn(c[half * 2 + 0], cv0);
                    float x1 = __fadd_rn(c[half * 2 + 1], cv1);
                    float p0 = __fadd_rn(__fmul_rn(0.5f, tanhf(__fmul_rn(0.5f, x0))), 0.5f);
                    float p1 = __fadd_rn(__fmul_rn(0.5f, tanhf(__fmul_rn(0.5f, x1))), 0.5f);
                    uint32_t gi = (uint32_t)rr * NH + col;
                    float u0 = bits_to_unit(rand_bits(key0, key1, gi));
                    float u1 = bits_to_unit(rand_bits(key0, key1, gi + 1));
                    uint32_t b0 = (u0 < p0) ? 0x3F80u : 0u;
                    uint32_t b1 = (u1 < p1) ? 0x3F80u : 0u;
                    *(uint32_t*)(g_hb + (size_t)rr * NH + col) = (b1 << 16) | b0;
                    if (fout)
                        *(float2*)(fout + (size_t)rr * NH + col) =
                            make_float2(b0 ? 1.0f : 0.0f, b1 ? 1.0f : 0.0f);
                }
            }
        }
    }
}

// ---------------- categorical (gumbel-argmax); writes bf16 one-hot into g_A ----------------
__global__ void k_categorical(uint32_t k0, uint32_t k1,
                              const float* __restrict__ bvec,
                              float* __restrict__ vout, int write_out) {
    int i = blockIdx.x * 256 + threadIdx.x;   // over B*V
    int b = i >> 9;
    int v = i & (NV - 1);

    float best = 0.0f;
    uint32_t bc = 0;
#pragma unroll
    for (int c = 0; c < NC; c++) {
        float l = __fadd_rn(g_logits[(size_t)b * NCV + c * NV + v], bvec[c * NV + v]);
        uint32_t gi = ((uint32_t)b * NC + c) * NV + v;
        float u = bits_to_unit(rand_bits(k0, k1, gi));
        float up = fmaxf(__fadd_rn(u, TINYF), TINYF);
        float gmb = -logf(-logf(up));
        float s = __fadd_rn(gmb, l);
        if (c == 0 || s > best) { best = s; bc = (uint32_t)c; }
    }
#pragma unroll
    for (int c = 0; c < NC; c++)
        g_A[(size_t)b * NCV + c * NV + v] =
            __float2bfloat16((c == (int)bc) ? 1.0f : 0.0f);
    if (write_out) {
#pragma unroll
        for (int c = 0; c < NC; c++)
            vout[(size_t)(b * NC + c) * NV + v] = (c == (int)bc) ? 1.0f : 0.0f;
    }
}

// ---------------- launcher ----------------
extern "C" void kernel_launch(void* const* d_in, const int* in_sizes, int n_in,
                              void* d_out, int out_size) {
    const float* v0 = (const float*)d_in[0];
    const float* W  = (const float*)d_in[1];
    const float* bb = (const float*)d_in[2];
    const float* cc = (const float*)d_in[3];
    (void)in_sizes; (void)n_in; (void)out_size;

    float* out    = (float*)d_out;
    float* out_v  = out;
    float* out_h  = out + (size_t)NBCV;
    float* out_h0 = out_h + (size_t)NBH;

    // keys = jax.random.split(jax.random.key(42), 5)  (partitionable)
    uint32_t keys[5][2];
    for (uint32_t i = 0; i < 5; i++)
        threefry(0u, 42u, 0u, i, keys[i][0], keys[i][1]);

    cudaFuncSetAttribute(k_mma<0>, cudaFuncAttributeMaxDynamicSharedMemorySize, SMEMB);
    cudaFuncSetAttribute(k_mma<1>, cudaFuncAttributeMaxDynamicSharedMemorySize, SMEMB);

    void *pA, *pHB, *pWt, *pWh, *pLog;
    cudaGetSymbolAddress(&pA, g_A);
    cudaGetSymbolAddress(&pHB, g_hb);
    cudaGetSymbolAddress(&pWt, g_Wt3);
    cudaGetSymbolAddress(&pWh, g_Wh3);
    cudaGetSymbolAddress(&pLog, g_logits);
    const __nv_bfloat16* A   = (const __nv_bfloat16*)pA;
    const __nv_bfloat16* HB  = (const __nv_bfloat16*)pHB;
    const __nv_bfloat16* Wt3 = (const __nv_bfloat16*)pWt;
    const __nv_bfloat16* Wh3 = (const __nv_bfloat16*)pWh;
    float* LOG = (float*)pLog;

    dim3 gh(NH / BN, NB / BM);     // (4, 128)  sample_h GEMM
    dim3 gv(NCV / BN, NB / BM);    // (40, 128) sample_v GEMM

    k_prep_wt<<<NCV * NH / 256, 256>>>(W);
    k_prep_wh<<<dim3(NCV / 256, NH), 256>>>(W);
    k_cast_A0<<<NBCV / 1024, 256>>>(v0);

    // h = sample_h(keys[0], v0) -> out_h0
    k_mma<1><<<gh, 256, SMEMB>>>(A, NCV, Wh3, NCV, NCV / BK,
                                 keys[0][0], keys[0][1], cc, out_h0);
    // iter 0
    k_mma<0><<<gv, 256, SMEMB>>>(HB, NH, Wt3, NH, NH / BK, 0, 0, nullptr, LOG);
    k_categorical<<<NB * NV / 256, 256>>>(keys[1][0], keys[1][1], bb, nullptr, 0);
    k_mma<1><<<gh, 256, SMEMB>>>(A, NCV, Wh3, NCV, NCV / BK,
                                 keys[2][0], keys[2][1], cc, nullptr);
    // iter 1
    k_mma<0><<<gv, 256, SMEMB>>>(HB, NH, Wt3, NH, NH / BK, 0, 0, nullptr, LOG);
    k_categorical<<<NB * NV / 256, 256>>>(keys[3][0], keys[3][1], bb, out_v, 1);
    k_mma<1><<<gh, 256, SMEMB>>>(A, NCV, Wh3, NCV, NCV / BK,
                                 keys[4][0], keys[4][1], cc, out_h);
}

// round 7
// speedup vs baseline: 2.5635x; 1.1963x over previous
#include <cuda_runtime.h>
#include <cuda_fp16.h>
#include <cstdint>
#include <math.h>

// Problem constants
#define NB 16384
#define NC 5
#define NH 256
#define NV 512
#define NCV 2560
#define NBH 4194304
#define NBCV 41943040u
#define TINYF 1.17549435082228751e-38f

// ---------------- scratch (static device globals) ----------------
__device__ __half g_A[(size_t)NB * NCV];     // one-hot v fp16 (A for sample_h, K=2560)
__device__ __half g_hb[(size_t)NB * NH];     // h fp16 (A for sample_v, K=256)
__device__ float  g_logits[(size_t)NB * NCV];
__device__ __half g_Wt2[2][NCV * NH];        // [split][cv][h]  (B for sample_v)
__device__ __half g_Wh2[2][NH * NCV];        // [split][h][cv]  (B for sample_h)

// ---------------- threefry2x32 (bit-exact with JAX, partitionable) ----------------
__host__ __device__ __forceinline__ uint32_t rotl32(uint32_t x, int r) {
#ifdef __CUDA_ARCH__
    return __funnelshift_l(x, x, r);
#else
    return (x << r) | (x >> (32 - r));
#endif
}

__host__ __device__ inline void threefry(uint32_t k0, uint32_t k1,
                                         uint32_t x0, uint32_t x1,
                                         uint32_t& o0, uint32_t& o1) {
    uint32_t k2 = k0 ^ k1 ^ 0x1BD11BDAu;
#define TFR(r) { x0 += x1; x1 = rotl32(x1, (r)); x1 ^= x0; }
    x0 += k0; x1 += k1;
    TFR(13) TFR(15) TFR(26) TFR(6)   x0 += k1; x1 += k2 + 1u;
    TFR(17) TFR(29) TFR(16) TFR(24)  x0 += k2; x1 += k0 + 2u;
    TFR(13) TFR(15) TFR(26) TFR(6)   x0 += k0; x1 += k1 + 3u;
    TFR(17) TFR(29) TFR(16) TFR(24)  x0 += k1; x1 += k2 + 4u;
    TFR(13) TFR(15) TFR(26) TFR(6)   x0 += k2; x1 += k0 + 5u;
#undef TFR
    o0 = x0; o1 = x1;
}

__device__ __forceinline__ uint32_t rand_bits(uint32_t k0, uint32_t k1, uint32_t i) {
    uint32_t a, b;
    threefry(k0, k1, 0u, i, a, b);
    return a ^ b;
}

__device__ __forceinline__ float bits_to_unit(uint32_t bits) {
    return __fadd_rn(__uint_as_float((bits >> 9) | 0x3f800000u), -1.0f);
}

// ---------------- small helpers ----------------
__device__ __forceinline__ uint32_t smem_u32(const void* p) {
    uint32_t a;
    asm("{ .reg .u64 t; cvta.to.shared.u64 t, %1; cvt.u32.u64 %0, t; }" : "=r"(a) : "l"(p));
    return a;
}

__device__ __forceinline__ void cp16(uint32_t s, const void* g) {
    asm volatile("cp.async.cg.shared.global [%0], [%1], 16;" :: "r"(s), "l"(g));
}
#define CP_COMMIT() asm volatile("cp.async.commit_group;" ::: "memory")
#define CP_WAIT(n)  asm volatile("cp.async.wait_group %0;" :: "n"(n) : "memory")

__device__ __forceinline__ void ldmx4(uint32_t* r, uint32_t addr) {
    asm volatile("ldmatrix.sync.aligned.m8n8.x4.shared.b16 {%0,%1,%2,%3}, [%4];"
                 : "=r"(r[0]), "=r"(r[1]), "=r"(r[2]), "=r"(r[3]) : "r"(addr));
}

__device__ __forceinline__ void mma16816(float* c, const uint32_t* a,
                                         uint32_t b0, uint32_t b1) {
    asm volatile(
        "mma.sync.aligned.m16n8k16.row.col.f32.f16.f16.f32 "
        "{%0,%1,%2,%3}, {%4,%5,%6,%7}, {%8,%9}, {%0,%1,%2,%3};"
        : "+f"(c[0]), "+f"(c[1]), "+f"(c[2]), "+f"(c[3])
        : "r"(a[0]), "r"(a[1]), "r"(a[2]), "r"(a[3]), "r"(b0), "r"(b1));
}

// ---------------- prep kernels ----------------
__device__ __forceinline__ void split2(float w, __half& a, __half& b) {
    a = __float2half_rn(w);
    float r1 = w - __half2float(a);
    b = __float2half_rn(r1);
}

__global__ void k_prep_wt(const float* __restrict__ W) {
    int i = blockIdx.x * 256 + threadIdx.x;   // over NCV*NH
    int h = i & (NH - 1);
    int cv = i >> 8;
    int v = cv & (NV - 1);
    int c = cv >> 9;
    __half a, b;
    split2(W[((size_t)(c * NH + h)) * NV + v], a, b);
    g_Wt2[0][i] = a; g_Wt2[1][i] = b;
}

__global__ void k_prep_wh(const float* __restrict__ W) {
    int cv = blockIdx.x * 256 + threadIdx.x;  // 0..2559
    int h  = blockIdx.y;
    int v = cv & (NV - 1);
    int c = cv >> 9;
    __half a, b;
    split2(W[((size_t)(c * NH + h)) * NV + v], a, b);
    size_t o = (size_t)h * NCV + cv;
    g_Wh2[0][o] = a; g_Wh2[1][o] = b;
}

__global__ void k_cast_A0(const float* __restrict__ v0) {
    size_t i = ((size_t)blockIdx.x * 256 + threadIdx.x) * 4;
    float4 f = *(const float4*)(v0 + i);
    __half o[4] = {__float2half_rn(f.x), __float2half_rn(f.y),
                   __float2half_rn(f.z), __float2half_rn(f.w)};
    *(uint2*)(g_A + i) = *(uint2*)o;
}

// ---------------- warp-MMA GEMM: D[128,64] += A[128,K] * sum_s Bs[64,K]^T ----------------
// EPI 0: store logits fp32.  EPI 1: bernoulli-h epilogue (sigmoid + threefry).
#define BM 128
#define BN 64
#define BK 32
#define ROWB 80                       // 32 fp16 (64B) + 16B pad -> conflict-free ldmatrix
#define ATILE (BM * ROWB)             // 10240
#define BTILE (BN * ROWB)             // 5120
#define STG (ATILE + 2 * BTILE)       // 20480 bytes per stage
#define NSTAGE 4
#define SMEMB (NSTAGE * STG)          // 81920
#define BSPLIT ((size_t)NCV * NH)

template<int EPI>
__global__ __launch_bounds__(256, 2)
void k_mma(const __half* __restrict__ Asrc, int lda,
           const __half* __restrict__ Bsrc, int ldb, int nk,
           uint32_t key0, uint32_t key1,
           const float* __restrict__ cvec,
           float* __restrict__ fout) {
    extern __shared__ char smem[];
    const uint32_t sb = smem_u32(smem);
    const int tid = threadIdx.x;
    const int lane = tid & 31;
    const int wid = tid >> 5;
    const int wm = wid & 3;            // 4 warps along M (32 rows each)
    const int wn = wid >> 2;           // 2 warps along N (32 cols each)
    const int bn = blockIdx.x * BN;
    const int bm = blockIdx.y * BM;

    // per-thread global/smem load mapping
    const int ar0 = tid >> 2;          // A rows: ar0, ar0+64
    const int ac  = (tid & 3) * 16;    // smem byte chunk
    const int ack = (tid & 3) * 8;     // gmem k-element offset
    const int br  = tid >> 2;          // B row 0..63

    // precomputed ldmatrix intra-tile offsets
    const uint32_t aoff = (uint32_t)((wm * 32 + (lane & 15)) * ROWB + (lane >> 4) * 16);
    const uint32_t boff = (uint32_t)((wn * 32 + (lane & 7) + ((lane >> 4) << 3)) * ROWB
                                     + ((lane >> 3) & 1) * 16);

    auto issue = [&](int kc) {
        const int k0 = kc * BK;
        uint32_t s = sb + (kc & (NSTAGE - 1)) * STG;
        cp16(s + ar0 * ROWB + ac,
             Asrc + (size_t)(bm + ar0) * lda + k0 + ack);
        cp16(s + (ar0 + 64) * ROWB + ac,
             Asrc + (size_t)(bm + ar0 + 64) * lda + k0 + ack);
#pragma unroll
        for (int sp = 0; sp < 2; sp++)
            cp16(s + ATILE + sp * BTILE + br * ROWB + ac,
                 Bsrc + sp * BSPLIT + (size_t)(bn + br) * ldb + k0 + ack);
    };

    float acc[2][4][4];
#pragma unroll
    for (int i = 0; i < 2; i++)
#pragma unroll
        for (int j = 0; j < 4; j++)
#pragma unroll
            for (int q = 0; q < 4; q++) acc[i][j][q] = 0.0f;

    // prologue: fill NSTAGE-1 stages
    issue(0); CP_COMMIT();
    issue(1); CP_COMMIT();
    issue(2); CP_COMMIT();

#pragma unroll 1
    for (int kc = 0; kc < nk; kc++) {
        CP_WAIT(2);                    // stage kc complete (<=2 groups pending)
        __syncthreads();
        // keep commit cadence constant (empty groups near the tail)
        if (kc + 3 < nk) issue(kc + 3);
        CP_COMMIT();

        const uint32_t sA = sb + (kc & (NSTAGE - 1)) * STG;
        const uint32_t sB = sA + ATILE;

        // ---- load ALL fragments for both k16 steps up front (12 LDSM) ----
        uint32_t a[2][2][4];           // [ks][mi]
        uint32_t b[2][2][2][4];        // [ks][sp][nh]
#pragma unroll
        for (int ks = 0; ks < 2; ks++) {
#pragma unroll
            for (int mi = 0; mi < 2; mi++)
                ldmx4(a[ks][mi], sA + aoff + (uint32_t)(mi * 16 * ROWB + ks * 32));
#pragma unroll
            for (int sp = 0; sp < 2; sp++)
#pragma unroll
                for (int nh = 0; nh < 2; nh++)
                    ldmx4(b[ks][sp][nh], sB + sp * BTILE + boff
                                         + (uint32_t)(nh * 16 * ROWB + ks * 32));
        }

        // ---- 32 back-to-back MMAs ----
#pragma unroll
        for (int ks = 0; ks < 2; ks++)
#pragma unroll
            for (int sp = 0; sp < 2; sp++)
#pragma unroll
                for (int nh = 0; nh < 2; nh++)
#pragma unroll
                    for (int mi = 0; mi < 2; mi++) {
                        mma16816(acc[mi][nh * 2 + 0], a[ks][mi],
                                 b[ks][sp][nh][0], b[ks][sp][nh][1]);
                        mma16816(acc[mi][nh * 2 + 1], a[ks][mi],
                                 b[ks][sp][nh][2], b[ks][sp][nh][3]);
                    }
    }

    // ---------------- epilogue ----------------
    const int r4 = lane >> 2;
    const int c2 = (lane & 3) * 2;
#pragma unroll
    for (int mi = 0; mi < 2; mi++) {
#pragma unroll
        for (int ni = 0; ni < 4; ni++) {
            const float* c = acc[mi][ni];
            const int col = bn + wn * 32 + ni * 8 + c2;
            const int row = bm + wm * 32 + mi * 16 + r4;
            if (EPI == 0) {
                *(float2*)(fout + (size_t)row * NCV + col)       = make_float2(c[0], c[1]);
                *(float2*)(fout + (size_t)(row + 8) * NCV + col) = make_float2(c[2], c[3]);
            } else {
                const float cv0 = cvec[col], cv1 = cvec[col + 1];
#pragma unroll
                for (int half_ = 0; half_ < 2; half_++) {
                    const int rr = row + half_ * 8;
                    float x0 = __fadd_rn(c[half_ * 2 + 0], cv0);
                    float x1 = __fadd_rn(c[half_ * 2 + 1], cv1);
                    float p0 = __fadd_rn(__fmul_rn(0.5f, tanhf(__fmul_rn(0.5f, x0))), 0.5f);
                    float p1 = __fadd_rn(__fmul_rn(0.5f, tanhf(__fmul_rn(0.5f, x1))), 0.5f);
                    uint32_t gi = (uint32_t)rr * NH + col;
                    float u0 = bits_to_unit(rand_bits(key0, key1, gi));
                    float u1 = bits_to_unit(rand_bits(key0, key1, gi + 1));
                    uint32_t b0 = (u0 < p0) ? 0x3C00u : 0u;   // fp16 1.0
                    uint32_t b1 = (u1 < p1) ? 0x3C00u : 0u;
                    *(uint32_t*)(g_hb + (size_t)rr * NH + col) = (b1 << 16) | b0;
                    if (fout)
                        *(float2*)(fout + (size_t)rr * NH + col) =
                            make_float2(b0 ? 1.0f : 0.0f, b1 ? 1.0f : 0.0f);
                }
            }
        }
    }
}

// ---------------- categorical (gumbel-argmax); writes fp16 one-hot into g_A ----------------
__global__ void k_categorical(uint32_t k0, uint32_t k1,
                              const float* __restrict__ bvec,
                              float* __restrict__ vout, int write_out) {
    int i = blockIdx.x * 256 + threadIdx.x;   // over B*V
    int b = i >> 9;
    int v = i & (NV - 1);

    float best = 0.0f;
    uint32_t bc = 0;
#pragma unroll
    for (int c = 0; c < NC; c++) {
        float l = __fadd_rn(g_logits[(size_t)b * NCV + c * NV + v], bvec[c * NV + v]);
        uint32_t gi = ((uint32_t)b * NC + c) * NV + v;
        float u = bits_to_unit(rand_bits(k0, k1, gi));
        float up = fmaxf(__fadd_rn(u, TINYF), TINYF);
        float gmb = -logf(-logf(up));
        float s = __fadd_rn(gmb, l);
        if (c == 0 || s > best) { best = s; bc = (uint32_t)c; }
    }
#pragma unroll
    for (int c = 0; c < NC; c++)
        g_A[(size_t)b * NCV + c * NV + v] =
            __ushort_as_half((c == (int)bc) ? (unsigned short)0x3C00u : (unsigned short)0u);
    if (write_out) {
#pragma unroll
        for (int c = 0; c < NC; c++)
            vout[(size_t)(b * NC + c) * NV + v] = (c == (int)bc) ? 1.0f : 0.0f;
    }
}

// ---------------- launcher ----------------
extern "C" void kernel_launch(void* const* d_in, const int* in_sizes, int n_in,
                              void* d_out, int out_size) {
    const float* v0 = (const float*)d_in[0];
    const float* W  = (const float*)d_in[1];
    const float* bb = (const float*)d_in[2];
    const float* cc = (const float*)d_in[3];
    (void)in_sizes; (void)n_in; (void)out_size;

    float* out    = (float*)d_out;
    float* out_v  = out;
    float* out_h  = out + (size_t)NBCV;
    float* out_h0 = out_h + (size_t)NBH;

    // keys = jax.random.split(jax.random.key(42), 5)  (partitionable)
    uint32_t keys[5][2];
    for (uint32_t i = 0; i < 5; i++)
        threefry(0u, 42u, 0u, i, keys[i][0], keys[i][1]);

    cudaFuncSetAttribute(k_mma<0>, cudaFuncAttributeMaxDynamicSharedMemorySize, SMEMB);
    cudaFuncSetAttribute(k_mma<1>, cudaFuncAttributeMaxDynamicSharedMemorySize, SMEMB);

    void *pA, *pHB, *pWt, *pWh, *pLog;
    cudaGetSymbolAddress(&pA, g_A);
    cudaGetSymbolAddress(&pHB, g_hb);
    cudaGetSymbolAddress(&pWt, g_Wt2);
    cudaGetSymbolAddress(&pWh, g_Wh2);
    cudaGetSymbolAddress(&pLog, g_logits);
    const __half* A   = (const __half*)pA;
    const __half* HB  = (const __half*)pHB;
    const __half* Wt2 = (const __half*)pWt;
    const __half* Wh2 = (const __half*)pWh;
    float* LOG = (float*)pLog;

    dim3 gh(NH / BN, NB / BM);     // (4, 128)  sample_h GEMM
    dim3 gv(NCV / BN, NB / BM);    // (40, 128) sample_v GEMM

    k_prep_wt<<<NCV * NH / 256, 256>>>(W);
    k_prep_wh<<<dim3(NCV / 256, NH), 256>>>(W);
    k_cast_A0<<<NBCV / 1024, 256>>>(v0);

    // h = sample_h(keys[0], v0) -> out_h0
    k_mma<1><<<gh, 256, SMEMB>>>(A, NCV, Wh2, NCV, NCV / BK,
                                 keys[0][0], keys[0][1], cc, out_h0);
    // iter 0
    k_mma<0><<<gv, 256, SMEMB>>>(HB, NH, Wt2, NH, NH / BK, 0, 0, nullptr, LOG);
    k_categorical<<<NB * NV / 256, 256>>>(keys[1][0], keys[1][1], bb, nullptr, 0);
    k_mma<1><<<gh, 256, SMEMB>>>(A, NCV, Wh2, NCV, NCV / BK,
                                 keys[2][0], keys[2][1], cc, nullptr);
    // iter 1
    k_mma<0><<<gv, 256, SMEMB>>>(HB, NH, Wt2, NH, NH / BK, 0, 0, nullptr, LOG);
    k_categorical<<<NB * NV / 256, 256>>>(keys[3][0], keys[3][1], bb, out_v, 1);
    k_mma<1><<<gh, 256, SMEMB>>>(A, NCV, Wh2, NCV, NCV / BK,
                                 keys[4][0], keys[4][1], cc, out_h);
}

// round 8
// speedup vs baseline: 2.7741x; 1.0822x over previous
#include <cuda_runtime.h>
#include <cuda_fp16.h>
#include <cstdint>
#include <math.h>

// Problem constants
#define NB 16384
#define NC 5
#define NH 256
#define NV 512
#define NCV 2560
#define NBH 4194304
#define NBCV 41943040u
#define TINYF 1.17549435082228751e-38f

// ---------------- scratch (static device globals) ----------------
__device__ __half g_A[(size_t)NB * NCV];     // one-hot v fp16 (A for sample_h, K=2560)
__device__ __half g_hb[(size_t)NB * NH];     // h fp16 (A for sample_v, K=256)
__device__ float  g_logits[(size_t)NB * NCV];
__device__ __half g_Wt2[2][NCV * NH];        // [split][cv][h]  (B for sample_v)
__device__ __half g_Wh2[2][NH * NCV];        // [split][h][cv]  (B for sample_h)

// ---------------- threefry2x32 (bit-exact with JAX, partitionable) ----------------
__host__ __device__ __forceinline__ uint32_t rotl32(uint32_t x, int r) {
#ifdef __CUDA_ARCH__
    return __funnelshift_l(x, x, r);
#else
    return (x << r) | (x >> (32 - r));
#endif
}

__host__ __device__ inline void threefry(uint32_t k0, uint32_t k1,
                                         uint32_t x0, uint32_t x1,
                                         uint32_t& o0, uint32_t& o1) {
    uint32_t k2 = k0 ^ k1 ^ 0x1BD11BDAu;
#define TFR(r) { x0 += x1; x1 = rotl32(x1, (r)); x1 ^= x0; }
    x0 += k0; x1 += k1;
    TFR(13) TFR(15) TFR(26) TFR(6)   x0 += k1; x1 += k2 + 1u;
    TFR(17) TFR(29) TFR(16) TFR(24)  x0 += k2; x1 += k0 + 2u;
    TFR(13) TFR(15) TFR(26) TFR(6)   x0 += k0; x1 += k1 + 3u;
    TFR(17) TFR(29) TFR(16) TFR(24)  x0 += k1; x1 += k2 + 4u;
    TFR(13) TFR(15) TFR(26) TFR(6)   x0 += k2; x1 += k0 + 5u;
#undef TFR
    o0 = x0; o1 = x1;
}

__device__ __forceinline__ uint32_t rand_bits(uint32_t k0, uint32_t k1, uint32_t i) {
    uint32_t a, b;
    threefry(k0, k1, 0u, i, a, b);
    return a ^ b;
}

__device__ __forceinline__ float bits_to_unit(uint32_t bits) {
    return __fadd_rn(__uint_as_float((bits >> 9) | 0x3f800000u), -1.0f);
}

// ---------------- small helpers ----------------
__device__ __forceinline__ uint32_t smem_u32(const void* p) {
    uint32_t a;
    asm("{ .reg .u64 t; cvta.to.shared.u64 t, %1; cvt.u32.u64 %0, t; }" : "=r"(a) : "l"(p));
    return a;
}

__device__ __forceinline__ void cp16(uint32_t s, const void* g) {
    asm volatile("cp.async.cg.shared.global [%0], [%1], 16;" :: "r"(s), "l"(g));
}
#define CP_COMMIT() asm volatile("cp.async.commit_group;" ::: "memory")
#define CP_WAIT(n)  asm volatile("cp.async.wait_group %0;" :: "n"(n) : "memory")

__device__ __forceinline__ void ldmx4(uint32_t* r, uint32_t addr) {
    asm volatile("ldmatrix.sync.aligned.m8n8.x4.shared.b16 {%0,%1,%2,%3}, [%4];"
                 : "=r"(r[0]), "=r"(r[1]), "=r"(r[2]), "=r"(r[3]) : "r"(addr));
}

__device__ __forceinline__ void mma16816(float* c, const uint32_t* a,
                                         uint32_t b0, uint32_t b1) {
    asm volatile(
        "mma.sync.aligned.m16n8k16.row.col.f32.f16.f16.f32 "
        "{%0,%1,%2,%3}, {%4,%5,%6,%7}, {%8,%9}, {%0,%1,%2,%3};"
        : "+f"(c[0]), "+f"(c[1]), "+f"(c[2]), "+f"(c[3])
        : "r"(a[0]), "r"(a[1]), "r"(a[2]), "r"(a[3]), "r"(b0), "r"(b1));
}

// ---------------- prep kernels ----------------
__device__ __forceinline__ void split2(float w, __half& a, __half& b) {
    a = __float2half_rn(w);
    float r1 = w - __half2float(a);
    b = __float2half_rn(r1);
}

__global__ void k_prep_wt(const float* __restrict__ W) {
    int i = blockIdx.x * 256 + threadIdx.x;   // over NCV*NH
    int h = i & (NH - 1);
    int cv = i >> 8;
    int v = cv & (NV - 1);
    int c = cv >> 9;
    __half a, b;
    split2(W[((size_t)(c * NH + h)) * NV + v], a, b);
    g_Wt2[0][i] = a; g_Wt2[1][i] = b;
}

__global__ void k_prep_wh(const float* __restrict__ W) {
    int cv = blockIdx.x * 256 + threadIdx.x;  // 0..2559
    int h  = blockIdx.y;
    int v = cv & (NV - 1);
    int c = cv >> 9;
    __half a, b;
    split2(W[((size_t)(c * NH + h)) * NV + v], a, b);
    size_t o = (size_t)h * NCV + cv;
    g_Wh2[0][o] = a; g_Wh2[1][o] = b;
}

__global__ void k_cast_A0(const float* __restrict__ v0) {
    size_t i = ((size_t)blockIdx.x * 256 + threadIdx.x) * 4;
    float4 f = *(const float4*)(v0 + i);
    __half o[4] = {__float2half_rn(f.x), __float2half_rn(f.y),
                   __float2half_rn(f.z), __float2half_rn(f.w)};
    *(uint2*)(g_A + i) = *(uint2*)o;
}

// ---------------- warp-MMA GEMM: D[128,64] += A[128,K] * sum_s Bs[64,K]^T ----------------
// EPI 0: store logits fp32.  EPI 1: bernoulli-h epilogue (sigmoid + threefry).
#define BM 128
#define BN 64
#define BK 32
#define ROWB 80                       // 32 fp16 (64B) + 16B pad -> conflict-free ldmatrix
#define ATILE (BM * ROWB)             // 10240
#define BTILE (BN * ROWB)             // 5120
#define STG (ATILE + 2 * BTILE)       // 20480 bytes per stage
#define NSTAGE 3
#define SMEMB (NSTAGE * STG)          // 61440 -> 3 CTAs/SM
#define BSPLIT ((size_t)NCV * NH)

template<int EPI>
__global__ __launch_bounds__(256, 3)
void k_mma(const __half* __restrict__ Asrc, int lda,
           const __half* __restrict__ Bsrc, int ldb, int nk,
           uint32_t key0, uint32_t key1,
           const float* __restrict__ cvec,
           float* __restrict__ fout) {
    extern __shared__ char smem[];
    const uint32_t sb = smem_u32(smem);
    const int tid = threadIdx.x;
    const int lane = tid & 31;
    const int wid = tid >> 5;
    const int wm = wid & 3;            // 4 warps along M (32 rows each)
    const int wn = wid >> 2;           // 2 warps along N (32 cols each)
    const int bn = blockIdx.x * BN;
    const int bm = blockIdx.y * BM;

    // per-thread global/smem load mapping
    const int ar0 = tid >> 2;          // A rows: ar0, ar0+64
    const int ac  = (tid & 3) * 16;    // smem byte chunk
    const int ack = (tid & 3) * 8;     // gmem k-element offset
    const int br  = tid >> 2;          // B row 0..63

    // precomputed ldmatrix intra-tile offsets
    const uint32_t aoff = (uint32_t)((wm * 32 + (lane & 15)) * ROWB + (lane >> 4) * 16);
    const uint32_t boff = (uint32_t)((wn * 32 + (lane & 7) + ((lane >> 4) << 3)) * ROWB
                                     + ((lane >> 3) & 1) * 16);

    auto issue = [&](int kc) {
        const int k0 = kc * BK;
        uint32_t s = sb + (kc % NSTAGE) * STG;
        cp16(s + ar0 * ROWB + ac,
             Asrc + (size_t)(bm + ar0) * lda + k0 + ack);
        cp16(s + (ar0 + 64) * ROWB + ac,
             Asrc + (size_t)(bm + ar0 + 64) * lda + k0 + ack);
#pragma unroll
        for (int sp = 0; sp < 2; sp++)
            cp16(s + ATILE + sp * BTILE + br * ROWB + ac,
                 Bsrc + sp * BSPLIT + (size_t)(bn + br) * ldb + k0 + ack);
    };

    float acc[2][4][4];
#pragma unroll
    for (int i = 0; i < 2; i++)
#pragma unroll
        for (int j = 0; j < 4; j++)
#pragma unroll
            for (int q = 0; q < 4; q++) acc[i][j][q] = 0.0f;

    // prologue: fill NSTAGE-1 stages
    issue(0); CP_COMMIT();
    issue(1); CP_COMMIT();

#pragma unroll 1
    for (int kc = 0; kc < nk; kc++) {
        CP_WAIT(1);                    // stage kc complete (<=1 group pending)
        __syncthreads();
        // keep commit cadence constant (empty groups near the tail)
        if (kc + 2 < nk) issue(kc + 2);
        CP_COMMIT();

        const uint32_t sA = sb + (kc % NSTAGE) * STG;
        const uint32_t sB = sA + ATILE;

        // MMA order per accumulator: ks -> sp -> nh -> mi (identical to R7)
#pragma unroll
        for (int ks = 0; ks < 2; ks++) {
            uint32_t a[2][4];
#pragma unroll
            for (int mi = 0; mi < 2; mi++)
                ldmx4(a[mi], sA + aoff + (uint32_t)(mi * 16 * ROWB + ks * 32));
#pragma unroll
            for (int sp = 0; sp < 2; sp++) {
                uint32_t b[2][4];
#pragma unroll
                for (int nh = 0; nh < 2; nh++)
                    ldmx4(b[nh], sB + sp * BTILE + boff
                                 + (uint32_t)(nh * 16 * ROWB + ks * 32));
#pragma unroll
                for (int nh = 0; nh < 2; nh++)
#pragma unroll
                    for (int mi = 0; mi < 2; mi++) {
                        mma16816(acc[mi][nh * 2 + 0], a[mi], b[nh][0], b[nh][1]);
                        mma16816(acc[mi][nh * 2 + 1], a[mi], b[nh][2], b[nh][3]);
                    }
            }
        }
    }

    // ---------------- epilogue ----------------
    const int r4 = lane >> 2;
    const int c2 = (lane & 3) * 2;
#pragma unroll
    for (int mi = 0; mi < 2; mi++) {
#pragma unroll
        for (int ni = 0; ni < 4; ni++) {
            const float* c = acc[mi][ni];
            const int col = bn + wn * 32 + ni * 8 + c2;
            const int row = bm + wm * 32 + mi * 16 + r4;
            if (EPI == 0) {
                *(float2*)(fout + (size_t)row * NCV + col)       = make_float2(c[0], c[1]);
                *(float2*)(fout + (size_t)(row + 8) * NCV + col) = make_float2(c[2], c[3]);
            } else {
                const float cv0 = cvec[col], cv1 = cvec[col + 1];
#pragma unroll
                for (int half_ = 0; half_ < 2; half_++) {
                    const int rr = row + half_ * 8;
                    float x0 = __fadd_rn(c[half_ * 2 + 0], cv0);
                    float x1 = __fadd_rn(c[half_ * 2 + 1], cv1);
                    float p0 = __fadd_rn(__fmul_rn(0.5f, tanhf(__fmul_rn(0.5f, x0))), 0.5f);
                    float p1 = __fadd_rn(__fmul_rn(0.5f, tanhf(__fmul_rn(0.5f, x1))), 0.5f);
                    uint32_t gi = (uint32_t)rr * NH + col;
                    float u0 = bits_to_unit(rand_bits(key0, key1, gi));
                    float u1 = bits_to_unit(rand_bits(key0, key1, gi + 1));
                    uint32_t b0 = (u0 < p0) ? 0x3C00u : 0u;   // fp16 1.0
                    uint32_t b1 = (u1 < p1) ? 0x3C00u : 0u;
                    *(uint32_t*)(g_hb + (size_t)rr * NH + col) = (b1 << 16) | b0;
                    if (fout)
                        *(float2*)(fout + (size_t)rr * NH + col) =
                            make_float2(b0 ? 1.0f : 0.0f, b1 ? 1.0f : 0.0f);
                }
            }
        }
    }
}

// ---------------- categorical (gumbel-argmax); writes fp16 one-hot into g_A ----------------
__global__ void k_categorical(uint32_t k0, uint32_t k1,
                              const float* __restrict__ bvec,
                              float* __restrict__ vout, int write_out) {
    int i = blockIdx.x * 256 + threadIdx.x;   // over B*V
    int b = i >> 9;
    int v = i & (NV - 1);

    float best = 0.0f;
    uint32_t bc = 0;
#pragma unroll
    for (int c = 0; c < NC; c++) {
        float l = __fadd_rn(g_logits[(size_t)b * NCV + c * NV + v], bvec[c * NV + v]);
        uint32_t gi = ((uint32_t)b * NC + c) * NV + v;
        float u = bits_to_unit(rand_bits(k0, k1, gi));
        float up = fmaxf(__fadd_rn(u, TINYF), TINYF);
        float gmb = -logf(-logf(up));
        float s = __fadd_rn(gmb, l);
        if (c == 0 || s > best) { best = s; bc = (uint32_t)c; }
    }
#pragma unroll
    for (int c = 0; c < NC; c++)
        g_A[(size_t)b * NCV + c * NV + v] =
            __ushort_as_half((c == (int)bc) ? (unsigned short)0x3C00u : (unsigned short)0u);
    if (write_out) {
#pragma unroll
        for (int c = 0; c < NC; c++)
            vout[(size_t)(b * NC + c) * NV + v] = (c == (int)bc) ? 1.0f : 0.0f;
    }
}

// ---------------- launcher ----------------
extern "C" void kernel_launch(void* const* d_in, const int* in_sizes, int n_in,
                              void* d_out, int out_size) {
    const float* v0 = (const float*)d_in[0];
    const float* W  = (const float*)d_in[1];
    const float* bb = (const float*)d_in[2];
    const float* cc = (const float*)d_in[3];
    (void)in_sizes; (void)n_in; (void)out_size;

    float* out    = (float*)d_out;
    float* out_v  = out;
    float* out_h  = out + (size_t)NBCV;
    float* out_h0 = out_h + (size_t)NBH;

    // keys = jax.random.split(jax.random.key(42), 5)  (partitionable)
    uint32_t keys[5][2];
    for (uint32_t i = 0; i < 5; i++)
        threefry(0u, 42u, 0u, i, keys[i][0], keys[i][1]);

    cudaFuncSetAttribute(k_mma<0>, cudaFuncAttributeMaxDynamicSharedMemorySize, SMEMB);
    cudaFuncSetAttribute(k_mma<1>, cudaFuncAttributeMaxDynamicSharedMemorySize, SMEMB);

    void *pA, *pHB, *pWt, *pWh, *pLog;
    cudaGetSymbolAddress(&pA, g_A);
    cudaGetSymbolAddress(&pHB, g_hb);
    cudaGetSymbolAddress(&pWt, g_Wt2);
    cudaGetSymbolAddress(&pWh, g_Wh2);
    cudaGetSymbolAddress(&pLog, g_logits);
    const __half* A   = (const __half*)pA;
    const __half* HB  = (const __half*)pHB;
    const __half* Wt2 = (const __half*)pWt;
    const __half* Wh2 = (const __half*)pWh;
    float* LOG = (float*)pLog;

    dim3 gh(NH / BN, NB / BM);     // (4, 128)  sample_h GEMM
    dim3 gv(NCV / BN, NB / BM);    // (40, 128) sample_v GEMM

    k_prep_wt<<<NCV * NH / 256, 256>>>(W);
    k_prep_wh<<<dim3(NCV / 256, NH), 256>>>(W);
    k_cast_A0<<<NBCV / 1024, 256>>>(v0);

    // h = sample_h(keys[0], v0) -> out_h0
    k_mma<1><<<gh, 256, SMEMB>>>(A, NCV, Wh2, NCV, NCV / BK,
                                 keys[0][0], keys[0][1], cc, out_h0);
    // iter 0
    k_mma<0><<<gv, 256, SMEMB>>>(HB, NH, Wt2, NH, NH / BK, 0, 0, nullptr, LOG);
    k_categorical<<<NB * NV / 256, 256>>>(keys[1][0], keys[1][1], bb, nullptr, 0);
    k_mma<1><<<gh, 256, SMEMB>>>(A, NCV, Wh2, NCV, NCV / BK,
                                 keys[2][0], keys[2][1], cc, nullptr);
    // iter 1
    k_mma<0><<<gv, 256, SMEMB>>>(HB, NH, Wt2, NH, NH / BK, 0, 0, nullptr, LOG);
    k_categorical<<<NB * NV / 256, 256>>>(keys[3][0], keys[3][1], bb, out_v, 1);
    k_mma<1><<<gh, 256, SMEMB>>>(A, NCV, Wh2, NCV, NCV / BK,
                                 keys[4][0], keys[4][1], cc, out_h);
}

// round 9
// speedup vs baseline: 3.1126x; 1.1220x over previous
#include <cuda_runtime.h>
#include <cuda_fp16.h>
#include <cstdint>
#include <math.h>

// Problem constants
#define NB 16384
#define NC 5
#define NH 256
#define NV 512
#define NCV 2560
#define NBH 4194304
#define NBCV 41943040u
#define TINYF 1.17549435082228751e-38f

// ---------------- scratch (static device globals) ----------------
__device__ __half g_A[(size_t)NB * NCV];     // one-hot v fp16 (A for sample_h, K=2560), cv = c*512+v
__device__ __half g_hb[(size_t)NB * NH];     // h fp16 (A for sample_v, K=256)
__device__ __half g_Wv2[2][NCV * NH];        // [split][v*5+c][h]  (B for sample_v, fused categorical)
__device__ __half g_Wh2[2][NH * NCV];        // [split][h][c*512+v] (B for sample_h)

// ---------------- threefry2x32 (bit-exact with JAX, partitionable) ----------------
__host__ __device__ __forceinline__ uint32_t rotl32(uint32_t x, int r) {
#ifdef __CUDA_ARCH__
    return __funnelshift_l(x, x, r);
#else
    return (x << r) | (x >> (32 - r));
#endif
}

__host__ __device__ inline void threefry(uint32_t k0, uint32_t k1,
                                         uint32_t x0, uint32_t x1,
                                         uint32_t& o0, uint32_t& o1) {
    uint32_t k2 = k0 ^ k1 ^ 0x1BD11BDAu;
#define TFR(r) { x0 += x1; x1 = rotl32(x1, (r)); x1 ^= x0; }
    x0 += k0; x1 += k1;
    TFR(13) TFR(15) TFR(26) TFR(6)   x0 += k1; x1 += k2 + 1u;
    TFR(17) TFR(29) TFR(16) TFR(24)  x0 += k2; x1 += k0 + 2u;
    TFR(13) TFR(15) TFR(26) TFR(6)   x0 += k0; x1 += k1 + 3u;
    TFR(17) TFR(29) TFR(16) TFR(24)  x0 += k1; x1 += k2 + 4u;
    TFR(13) TFR(15) TFR(26) TFR(6)   x0 += k2; x1 += k0 + 5u;
#undef TFR
    o0 = x0; o1 = x1;
}

__device__ __forceinline__ uint32_t rand_bits(uint32_t k0, uint32_t k1, uint32_t i) {
    uint32_t a, b;
    threefry(k0, k1, 0u, i, a, b);
    return a ^ b;
}

__device__ __forceinline__ float bits_to_unit(uint32_t bits) {
    return __fadd_rn(__uint_as_float((bits >> 9) | 0x3f800000u), -1.0f);
}

// ---------------- small helpers ----------------
__device__ __forceinline__ uint32_t smem_u32(const void* p) {
    uint32_t a;
    asm("{ .reg .u64 t; cvta.to.shared.u64 t, %1; cvt.u32.u64 %0, t; }" : "=r"(a) : "l"(p));
    return a;
}

__device__ __forceinline__ void cp16(uint32_t s, const void* g) {
    asm volatile("cp.async.cg.shared.global [%0], [%1], 16;" :: "r"(s), "l"(g));
}
#define CP_COMMIT() asm volatile("cp.async.commit_group;" ::: "memory")
#define CP_WAIT(n)  asm volatile("cp.async.wait_group %0;" :: "n"(n) : "memory")

__device__ __forceinline__ void ldmx4(uint32_t* r, uint32_t addr) {
    asm volatile("ldmatrix.sync.aligned.m8n8.x4.shared.b16 {%0,%1,%2,%3}, [%4];"
                 : "=r"(r[0]), "=r"(r[1]), "=r"(r[2]), "=r"(r[3]) : "r"(addr));
}

__device__ __forceinline__ void mma16816(float* c, const uint32_t* a,
                                         uint32_t b0, uint32_t b1) {
    asm volatile(
        "mma.sync.aligned.m16n8k16.row.col.f32.f16.f16.f32 "
        "{%0,%1,%2,%3}, {%4,%5,%6,%7}, {%8,%9}, {%0,%1,%2,%3};"
        : "+f"(c[0]), "+f"(c[1]), "+f"(c[2]), "+f"(c[3])
        : "r"(a[0]), "r"(a[1]), "r"(a[2]), "r"(a[3]), "r"(b0), "r"(b1));
}

// ---------------- prep kernels ----------------
__device__ __forceinline__ void split2(float w, __half& a, __half& b) {
    a = __float2half_rn(w);
    float r1 = w - __half2float(a);
    b = __float2half_rn(r1);
}

// g_Wv2: row index = v*5 + c (argmax-self-contained 80-col tiles)
__global__ void k_prep_wv(const float* __restrict__ W) {
    int i = blockIdx.x * 256 + threadIdx.x;   // over NCV*NH
    int h = i & (NH - 1);
    int row = i >> 8;                         // v*5 + c
    int c = row % NC;
    int v = row / NC;
    __half a, b;
    split2(W[((size_t)(c * NH + h)) * NV + v], a, b);
    g_Wv2[0][i] = a; g_Wv2[1][i] = b;
}

__global__ void k_prep_wh(const float* __restrict__ W) {
    int cv = blockIdx.x * 256 + threadIdx.x;  // 0..2559  (c*512+v)
    int h  = blockIdx.y;
    int v = cv & (NV - 1);
    int c = cv >> 9;
    __half a, b;
    split2(W[((size_t)(c * NH + h)) * NV + v], a, b);
    size_t o = (size_t)h * NCV + cv;
    g_Wh2[0][o] = a; g_Wh2[1][o] = b;
}

__global__ void k_cast_A0(const float* __restrict__ v0) {
    size_t i = ((size_t)blockIdx.x * 256 + threadIdx.x) * 4;
    float4 f = *(const float4*)(v0 + i);
    __half o[4] = {__float2half_rn(f.x), __float2half_rn(f.y),
                   __float2half_rn(f.z), __float2half_rn(f.w)};
    *(uint2*)(g_A + i) = *(uint2*)o;
}

// ---------------- shared tiling constants ----------------
#define BM 128
#define BK 32
#define ROWB 80                       // 32 fp16 (64B) + 16B pad -> conflict-free ldmatrix
#define ATILE (BM * ROWB)             // 10240
#define BSPLIT ((size_t)NCV * NH)

// ======================= sample_h GEMM (BN=64) =======================
#define BN 64
#define BTILE (BN * ROWB)             // 5120
#define STG (ATILE + 2 * BTILE)       // 20480
#define NSTAGE 3
#define SMEMB (NSTAGE * STG)          // 61440

__global__ __launch_bounds__(256, 3)
void k_mma_h(const __half* __restrict__ Asrc, int lda,
             const __half* __restrict__ Bsrc, int ldb, int nk,
             uint32_t key0, uint32_t key1,
             const float* __restrict__ cvec,
             float* __restrict__ fout) {
    extern __shared__ char smem[];
    const uint32_t sb = smem_u32(smem);
    const int tid = threadIdx.x;
    const int lane = tid & 31;
    const int wid = tid >> 5;
    const int wm = wid & 3;
    const int wn = wid >> 2;
    const int bn = blockIdx.x * BN;
    const int bm = blockIdx.y * BM;

    const int ar0 = tid >> 2;
    const int ac  = (tid & 3) * 16;
    const int ack = (tid & 3) * 8;
    const int br  = tid >> 2;

    const uint32_t aoff = (uint32_t)((wm * 32 + (lane & 15)) * ROWB + (lane >> 4) * 16);
    const uint32_t boff = (uint32_t)((wn * 32 + (lane & 7) + ((lane >> 4) << 3)) * ROWB
                                     + ((lane >> 3) & 1) * 16);

    auto issue = [&](int kc) {
        const int k0 = kc * BK;
        uint32_t s = sb + (kc % NSTAGE) * STG;
        cp16(s + ar0 * ROWB + ac,        Asrc + (size_t)(bm + ar0) * lda + k0 + ack);
        cp16(s + (ar0 + 64) * ROWB + ac, Asrc + (size_t)(bm + ar0 + 64) * lda + k0 + ack);
#pragma unroll
        for (int sp = 0; sp < 2; sp++)
            cp16(s + ATILE + sp * BTILE + br * ROWB + ac,
                 Bsrc + sp * BSPLIT + (size_t)(bn + br) * ldb + k0 + ack);
    };

    float acc[2][4][4];
#pragma unroll
    for (int i = 0; i < 2; i++)
#pragma unroll
        for (int j = 0; j < 4; j++)
#pragma unroll
            for (int q = 0; q < 4; q++) acc[i][j][q] = 0.0f;

    issue(0); CP_COMMIT();
    issue(1); CP_COMMIT();

#pragma unroll 1
    for (int kc = 0; kc < nk; kc++) {
        CP_WAIT(1);
        __syncthreads();
        if (kc + 2 < nk) issue(kc + 2);
        CP_COMMIT();

        const uint32_t sA = sb + (kc % NSTAGE) * STG;
        const uint32_t sB = sA + ATILE;

#pragma unroll
        for (int ks = 0; ks < 2; ks++) {
            uint32_t a[2][4];
#pragma unroll
            for (int mi = 0; mi < 2; mi++)
                ldmx4(a[mi], sA + aoff + (uint32_t)(mi * 16 * ROWB + ks * 32));
#pragma unroll
            for (int sp = 0; sp < 2; sp++) {
                uint32_t b[2][4];
#pragma unroll
                for (int nh = 0; nh < 2; nh++)
                    ldmx4(b[nh], sB + sp * BTILE + boff
                                 + (uint32_t)(nh * 16 * ROWB + ks * 32));
#pragma unroll
                for (int nh = 0; nh < 2; nh++)
#pragma unroll
                    for (int mi = 0; mi < 2; mi++) {
                        mma16816(acc[mi][nh * 2 + 0], a[mi], b[nh][0], b[nh][1]);
                        mma16816(acc[mi][nh * 2 + 1], a[mi], b[nh][2], b[nh][3]);
                    }
            }
        }
    }

    // epilogue: sigmoid + threefry bernoulli
    const int r4 = lane >> 2;
    const int c2 = (lane & 3) * 2;
#pragma unroll
    for (int mi = 0; mi < 2; mi++) {
#pragma unroll
        for (int ni = 0; ni < 4; ni++) {
            const float* c = acc[mi][ni];
            const int col = bn + wn * 32 + ni * 8 + c2;
            const int row = bm + wm * 32 + mi * 16 + r4;
            const float cv0 = cvec[col], cv1 = cvec[col + 1];
#pragma unroll
            for (int half_ = 0; half_ < 2; half_++) {
                const int rr = row + half_ * 8;
                float x0 = __fadd_rn(c[half_ * 2 + 0], cv0);
                float x1 = __fadd_rn(c[half_ * 2 + 1], cv1);
                float p0 = __fadd_rn(__fmul_rn(0.5f, tanhf(__fmul_rn(0.5f, x0))), 0.5f);
                float p1 = __fadd_rn(__fmul_rn(0.5f, tanhf(__fmul_rn(0.5f, x1))), 0.5f);
                uint32_t gi = (uint32_t)rr * NH + col;
                float u0 = bits_to_unit(rand_bits(key0, key1, gi));
                float u1 = bits_to_unit(rand_bits(key0, key1, gi + 1));
                uint32_t b0 = (u0 < p0) ? 0x3C00u : 0u;
                uint32_t b1 = (u1 < p1) ? 0x3C00u : 0u;
                *(uint32_t*)(g_hb + (size_t)rr * NH + col) = (b1 << 16) | b0;
                if (fout)
                    *(float2*)(fout + (size_t)rr * NH + col) =
                        make_float2(b0 ? 1.0f : 0.0f, b1 ? 1.0f : 0.0f);
            }
        }
    }
}

// ============ sample_v GEMM + fused gumbel-argmax categorical (BN=80) ============
#define BNV 80
#define BTILEV (BNV * ROWB)            // 6400
#define STGV (ATILE + 2 * BTILEV)      // 23040
#define SMEMV (3 * STGV)               // 69120
#define TS 84                          // epilogue fp32 tile stride (floats)

template<int WRITE_OUT>
__global__ __launch_bounds__(256, 3)
void k_mma_v(const __half* __restrict__ Asrc,   // g_hb, lda = NH
             const __half* __restrict__ Bsrc,   // g_Wv2, rows v*5+c, ldb = NH
             uint32_t key0, uint32_t key1,
             const float* __restrict__ bvec,
             float* __restrict__ vout) {
    extern __shared__ char smem[];
    const uint32_t sb = smem_u32(smem);
    float* tile = (float*)smem;
    const int tid = threadIdx.x;
    const int lane = tid & 31;
    const int wid = tid >> 5;          // 8 warps, each M=16 rows, full N=80
    const int bn = blockIdx.x * BNV;   // cv' base (v*5+c)
    const int bm = blockIdx.y * BM;
    const int nk = NH / BK;            // 8

    const int ar0 = tid >> 2;
    const int ac  = (tid & 3) * 16;
    const int ack = (tid & 3) * 8;

    const uint32_t aoff = (uint32_t)((wid * 16 + (lane & 15)) * ROWB + (lane >> 4) * 16);
    const uint32_t boff = (uint32_t)(((lane & 7) + ((lane >> 4) << 3)) * ROWB
                                     + ((lane >> 3) & 1) * 16);

    auto issue = [&](int kc) {
        const int k0 = kc * BK;
        uint32_t s = sb + (kc % 3) * STGV;
        cp16(s + ar0 * ROWB + ac,        Asrc + (size_t)(bm + ar0) * NH + k0 + ack);
        cp16(s + (ar0 + 64) * ROWB + ac, Asrc + (size_t)(bm + ar0 + 64) * NH + k0 + ack);
#pragma unroll
        for (int sp = 0; sp < 2; sp++) {
#pragma unroll
            for (int i = 0; i < 2; i++) {
                int slot = tid + 256 * i;
                if (slot < 4 * BNV) {
                    int row = slot >> 2, col16 = (slot & 3) * 16;
                    cp16(s + ATILE + sp * BTILEV + row * ROWB + col16,
                         Bsrc + sp * BSPLIT + (size_t)(bn + row) * NH + k0 + (slot & 3) * 8);
                }
            }
        }
    };

    float acc[10][4];
#pragma unroll
    for (int j = 0; j < 10; j++)
#pragma unroll
        for (int q = 0; q < 4; q++) acc[j][q] = 0.0f;

    issue(0); CP_COMMIT();
    issue(1); CP_COMMIT();

#pragma unroll 1
    for (int kc = 0; kc < nk; kc++) {
        CP_WAIT(1);
        __syncthreads();
        if (kc + 2 < nk) issue(kc + 2);
        CP_COMMIT();

        const uint32_t sA = sb + (kc % 3) * STGV;
        const uint32_t sB = sA + ATILE;

        // per accumulator k-order: kc -> ks -> sp (identical to previous rounds)
#pragma unroll
        for (int ks = 0; ks < 2; ks++) {
            uint32_t a[4];
            ldmx4(a, sA + aoff + (uint32_t)(ks * 32));
#pragma unroll
            for (int sp = 0; sp < 2; sp++) {
#pragma unroll
                for (int g = 0; g < 5; g++) {
                    uint32_t b[4];
                    ldmx4(b, sB + sp * BTILEV + boff
                             + (uint32_t)(g * 16 * ROWB + ks * 32));
                    mma16816(acc[g * 2 + 0], a, b[0], b[1]);
                    mma16816(acc[g * 2 + 1], a, b[2], b[3]);
                }
            }
        }
    }

    // ---- epilogue: acc -> smem fp32 tile -> gumbel argmax over c ----
    __syncthreads();                       // stage buffers may still be read by other warps
    const int r4 = lane >> 2;
    const int c2 = (lane & 3) * 2;
    const int rw = wid * 16 + r4;
#pragma unroll
    for (int g = 0; g < 10; g++) {
        int col = g * 8 + c2;
        *(float2*)(tile + rw * TS + col)       = make_float2(acc[g][0], acc[g][1]);
        *(float2*)(tile + (rw + 8) * TS + col) = make_float2(acc[g][2], acc[g][3]);
    }
    __syncthreads();

    const int v0g = blockIdx.x * 16;       // 16 v's per CTA tile
#pragma unroll 1
    for (int j = 0; j < 8; j++) {
        int idx = tid + 256 * j;           // over 128 rows x 16 v
        int r  = idx >> 4;
        int vl = idx & 15;
        int bg = bm + r;
        int vg = v0g + vl;
        float best = 0.0f;
        uint32_t bc = 0;
#pragma unroll
        for (int c = 0; c < NC; c++) {
            float l = __fadd_rn(tile[r * TS + vl * NC + c], bvec[c * NV + vg]);
            uint32_t gi = (((uint32_t)bg * NC + (uint32_t)c) << 9) + (uint32_t)vg;
            float u = bits_to_unit(rand_bits(key0, key1, gi));
            float up = fmaxf(__fadd_rn(u, TINYF), TINYF);
            float gmb = -logf(-logf(up));
            float s = __fadd_rn(gmb, l);
            if (c == 0 || s > best) { best = s; bc = (uint32_t)c; }
        }
#pragma unroll
        for (int c = 0; c < NC; c++) {
            g_A[(size_t)bg * NCV + c * NV + vg] =
                __ushort_as_half((c == (int)bc) ? (unsigned short)0x3C00u : (unsigned short)0u);
            if (WRITE_OUT)
                vout[(size_t)bg * NCV + c * NV + vg] = (c == (int)bc) ? 1.0f : 0.0f;
        }
    }
}

// ---------------- launcher ----------------
extern "C" void kernel_launch(void* const* d_in, const int* in_sizes, int n_in,
                              void* d_out, int out_size) {
    const float* v0 = (const float*)d_in[0];
    const float* W  = (const float*)d_in[1];
    const float* bb = (const float*)d_in[2];
    const float* cc = (const float*)d_in[3];
    (void)in_sizes; (void)n_in; (void)out_size;

    float* out    = (float*)d_out;
    float* out_v  = out;
    float* out_h  = out + (size_t)NBCV;
    float* out_h0 = out_h + (size_t)NBH;

    // keys = jax.random.split(jax.random.key(42), 5)  (partitionable)
    uint32_t keys[5][2];
    for (uint32_t i = 0; i < 5; i++)
        threefry(0u, 42u, 0u, i, keys[i][0], keys[i][1]);

    cudaFuncSetAttribute(k_mma_h,    cudaFuncAttributeMaxDynamicSharedMemorySize, SMEMB);
    cudaFuncSetAttribute(k_mma_v<0>, cudaFuncAttributeMaxDynamicSharedMemorySize, SMEMV);
    cudaFuncSetAttribute(k_mma_v<1>, cudaFuncAttributeMaxDynamicSharedMemorySize, SMEMV);

    void *pA, *pHB, *pWv, *pWh;
    cudaGetSymbolAddress(&pA, g_A);
    cudaGetSymbolAddress(&pHB, g_hb);
    cudaGetSymbolAddress(&pWv, g_Wv2);
    cudaGetSymbolAddress(&pWh, g_Wh2);
    const __half* A   = (const __half*)pA;
    const __half* HB  = (const __half*)pHB;
    const __half* Wv2 = (const __half*)pWv;
    const __half* Wh2 = (const __half*)pWh;

    dim3 gh(NH / BN, NB / BM);      // (4, 128)   sample_h GEMM
    dim3 gv(NCV / BNV, NB / BM);    // (32, 128)  sample_v GEMM + categorical

    k_prep_wv<<<NCV * NH / 256, 256>>>(W);
    k_prep_wh<<<dim3(NCV / 256, NH), 256>>>(W);
    k_cast_A0<<<NBCV / 1024, 256>>>(v0);

    // h = sample_h(keys[0], v0) -> out_h0
    k_mma_h<<<gh, 256, SMEMB>>>(A, NCV, Wh2, NCV, NCV / BK,
                                keys[0][0], keys[0][1], cc, out_h0);
    // iter 0
    k_mma_v<0><<<gv, 256, SMEMV>>>(HB, Wv2, keys[1][0], keys[1][1], bb, nullptr);
    k_mma_h<<<gh, 256, SMEMB>>>(A, NCV, Wh2, NCV, NCV / BK,
                                keys[2][0], keys[2][1], cc, nullptr);
    // iter 1
    k_mma_v<1><<<gv, 256, SMEMV>>>(HB, Wv2, keys[3][0], keys[3][1], bb, out_v);
    k_mma_h<<<gh, 256, SMEMB>>>(A, NCV, Wh2, NCV, NCV / BK,
                                keys[4][0], keys[4][1], cc, out_h);
}